// round 9
// baseline (speedup 1.0000x reference)
#include <cuda_runtime.h>
#include <cuda_bf16.h>
#include <cstdint>

#define BB 16
#define CC 128
#define HH 56
#define WWI 56
#define TOK (BB*HH*WWI)          // 50176
#define QKC 128
#define QKVC 384
#define NWIN 7
#define WHS 8
#define P2 49
#define W2 64
#define TOPK 4
#define HEADS 4
#define HD 32
#define SCALE 0.08838834764831845f

typedef unsigned long long ull;

// ---------------- scratch (device globals; no allocation) ----------------
__device__ float g_xh [TOK*CC];
__device__ float g_qkv[TOK*QKVC];
__device__ float g_att[TOK*CC];
__device__ float g_qwin[BB*P2*CC];
__device__ float g_kwin[BB*P2*CC];
__device__ int   g_idx [BB*P2*TOPK];
// split-bf16 activations
__device__ __nv_bfloat16 g_yh [TOK*CC],  g_yl [TOK*CC];
__device__ __nv_bfloat16 g_ath[TOK*CC],  g_atl[TOK*CC];
__device__ __nv_bfloat16 g_h1h[TOK*3*CC],g_h1l[TOK*3*CC];
// split-bf16 weights, transposed to [N,K]
__device__ __nv_bfloat16 g_wqh[QKVC*CC], g_wql[QKVC*CC];
__device__ __nv_bfloat16 g_woh[CC*CC],   g_wol[CC*CC];
__device__ __nv_bfloat16 g_w1h[3*CC*CC], g_w1l[3*CC*CC];
__device__ __nv_bfloat16 g_w2h[CC*3*CC], g_w2l[CC*3*CC];

// ---------------- helpers ----------------
__device__ __forceinline__ uint32_t smem_u32(const void* p){
    uint32_t a;
    asm("{ .reg .u64 t; cvta.to.shared.u64 t, %1; cvt.u32.u64 %0, t; }" : "=r"(a) : "l"(p));
    return a;
}
__device__ __forceinline__ void ldm_x4(uint32_t& r0,uint32_t& r1,uint32_t& r2,uint32_t& r3, uint32_t addr){
    asm volatile("ldmatrix.sync.aligned.m8n8.x4.shared.b16 {%0,%1,%2,%3}, [%4];"
        : "=r"(r0),"=r"(r1),"=r"(r2),"=r"(r3) : "r"(addr));
}
__device__ __forceinline__ void ldm_x4_t(uint32_t& r0,uint32_t& r1,uint32_t& r2,uint32_t& r3, uint32_t addr){
    asm volatile("ldmatrix.sync.aligned.m8n8.x4.trans.shared.b16 {%0,%1,%2,%3}, [%4];"
        : "=r"(r0),"=r"(r1),"=r"(r2),"=r"(r3) : "r"(addr));
}
__device__ __forceinline__ void mma_bf16(float* d, const uint32_t* a, const uint32_t* b){
    asm volatile("mma.sync.aligned.m16n8k16.row.col.f32.bf16.bf16.f32 "
        "{%0,%1,%2,%3}, {%4,%5,%6,%7}, {%8,%9}, {%0,%1,%2,%3};"
        : "+f"(d[0]),"+f"(d[1]),"+f"(d[2]),"+f"(d[3])
        : "r"(a[0]),"r"(a[1]),"r"(a[2]),"r"(a[3]), "r"(b[0]),"r"(b[1]));
}
__device__ __forceinline__ uint32_t packbf2(float lo, float hi){
    uint32_t r;
    asm("cvt.rn.bf16x2.f32 %0, %1, %2;" : "=r"(r) : "f"(hi), "f"(lo));
    return r;
}
__device__ __forceinline__ void cp16(uint32_t saddr, const void* gaddr){
    asm volatile("cp.async.cg.shared.global [%0], [%1], 16;" :: "r"(saddr), "l"(gaddr));
}
__device__ __forceinline__ void cp_commit(){ asm volatile("cp.async.commit_group;"); }
template<int N> __device__ __forceinline__ void cp_wait(){
    asm volatile("cp.async.wait_group %0;" :: "n"(N));
}
__device__ __forceinline__ float gelu_exact(float v){
    return 0.5f * v * (1.0f + erff(v * 0.70710678118654752f));
}
__device__ __forceinline__ void split_bf16(float v, __nv_bfloat16& h, __nv_bfloat16& l){
    h = __float2bfloat16(v);
    l = __float2bfloat16(v - __bfloat162float(h));
}

// ---------------- fused weight transpose + split (one launch) ----------------
__global__ __launch_bounds__(256) void k_wsplit_all(
    const float* __restrict__ qkv_w, const float* __restrict__ wo_w,
    const float* __restrict__ mlp_w1, const float* __restrict__ mlp_w2,
    __nv_bfloat16* __restrict__ wqh, __nv_bfloat16* __restrict__ wql,
    __nv_bfloat16* __restrict__ woh, __nv_bfloat16* __restrict__ wol,
    __nv_bfloat16* __restrict__ w1h, __nv_bfloat16* __restrict__ w1l,
    __nv_bfloat16* __restrict__ w2h, __nv_bfloat16* __restrict__ w2l)
{
    int blk = blockIdx.x;
    const float* src; __nv_bfloat16 *dh, *dl; int K, N, base;
    if (blk < 192)      { src = qkv_w;  dh = wqh; dl = wql; K = CC;   N = QKVC; base = 0;   }
    else if (blk < 256) { src = wo_w;   dh = woh; dl = wol; K = CC;   N = CC;   base = 192; }
    else if (blk < 448) { src = mlp_w1; dh = w1h; dl = w1l; K = CC;   N = 3*CC; base = 256; }
    else                { src = mlp_w2; dh = w2h; dl = w2l; K = 3*CC; N = CC;   base = 448; }
    int i = (blk - base) * 256 + threadIdx.x;
    if (i >= N * K) return;
    int n = i / K, k = i - n * K;
    float v = src[(size_t)k * N + n];
    __nv_bfloat16 h, l; split_bf16(v, h, l);
    dh[i] = h; dl[i] = l;
}

// ---------------- kernel 1: x + dwconv3x3(x) -> xh (NHWC) ----------------
__global__ __launch_bounds__(256) void k_posconv(const float* __restrict__ x,
                                                 const float* __restrict__ pw,
                                                 const float* __restrict__ pb,
                                                 float* __restrict__ xh){
    __shared__ __align__(16) float s[3*64*57];
    int bh = blockIdx.x; int b = bh / HH, h = bh % HH;
    int c0 = blockIdx.y * 64;
    int tid = threadIdx.x;
    for (int l = tid; l < 3*64*56; l += 256){
        int row = l / (64*56);
        int rem = l - row*(64*56);
        int c   = rem / 56;
        int wv  = rem - c*56;
        int hr  = h + row - 1;
        float v = 0.f;
        if (hr >= 0 && hr < HH)
            v = x[((size_t)((b*CC + c0 + c)*HH + hr))*WWI + wv];
        s[row*64*57 + c*57 + wv] = v;
    }
    __syncthreads();
    int c = tid & 63;
    float wgt[9];
    #pragma unroll
    for (int t = 0; t < 9; t++) wgt[t] = pw[(c0 + c)*9 + t];
    float bias = pb[c0 + c];
    for (int l = tid; l < 56*64; l += 256){
        int w = l >> 6;
        float acc = bias;
        #pragma unroll
        for (int ky = 0; ky < 3; ky++){
            const float* srow = &s[ky*64*57 + c*57];
            #pragma unroll
            for (int kx = 0; kx < 3; kx++){
                int ww = w + kx - 1;
                if (ww >= 0 && ww < WWI) acc += wgt[ky*3+kx] * srow[ww];
            }
        }
        acc += s[1*64*57 + c*57 + w];   // residual (center x)
        xh[((size_t)((b*HH + h)*WWI + w))*CC + c0 + c] = acc;
    }
}

// ---------------- kernel 2: LayerNorm over C -> split bf16 ----------------
__global__ __launch_bounds__(256) void k_ln(const float* __restrict__ in,
                                            const float* __restrict__ g,
                                            const float* __restrict__ bt,
                                            __nv_bfloat16* __restrict__ oh,
                                            __nv_bfloat16* __restrict__ ol){
    int warp = threadIdx.x >> 5, lane = threadIdx.x & 31;
    int tok = blockIdx.x * 8 + warp;
    const float4* ip = (const float4*)(in + (size_t)tok * CC);
    float4 v = ip[lane];
    float s = v.x + v.y + v.z + v.w;
    float q = v.x*v.x + v.y*v.y + v.z*v.z + v.w*v.w;
    #pragma unroll
    for (int o = 16; o; o >>= 1){
        s += __shfl_xor_sync(0xffffffffu, s, o);
        q += __shfl_xor_sync(0xffffffffu, q, o);
    }
    float m   = s * (1.f/128.f);
    float var = q * (1.f/128.f) - m*m;
    float r   = rsqrtf(var + 1e-6f);
    float4 gg = ((const float4*)g)[lane];
    float4 bb = ((const float4*)bt)[lane];
    float o0 = (v.x - m)*r*gg.x + bb.x;
    float o1 = (v.y - m)*r*gg.y + bb.y;
    float o2 = (v.z - m)*r*gg.z + bb.z;
    float o3 = (v.w - m)*r*gg.w + bb.w;
    __nv_bfloat16 h0,h1,h2,h3,l0,l1,l2,l3;
    split_bf16(o0,h0,l0); split_bf16(o1,h1,l1); split_bf16(o2,h2,l2); split_bf16(o3,h3,l3);
    size_t off = (size_t)tok * CC + lane*4;
    *(__nv_bfloat162*)(oh + off)     = __nv_bfloat162(h0, h1);
    *(__nv_bfloat162*)(oh + off + 2) = __nv_bfloat162(h2, h3);
    *(__nv_bfloat162*)(ol + off)     = __nv_bfloat162(l0, l1);
    *(__nv_bfloat162*)(ol + off + 2) = __nv_bfloat162(l2, l3);
}

// ---------------- HMMA GEMM: 128x128 CTA tile, cp.async double-buffered ----------------
// A: hi/lo bf16 [M,K] row-major. B: hi/lo bf16 [N,K] row-major (= col-major KxN operand).
// TERMS: 3 = Ah*Bh + Al*Bh + Ah*Bl ; 2 = Ah*Bh + Al*Bh
// EPI: 0 = bias -> fp32 C ; 1 = bias+GELU -> split bf16 (C1,C2) ; 2 = bias+residual R -> fp32 C
#define BSTR 72                  // smem row stride in bf16 (144B: conflict-free ldmatrix)
#define SLOT (128*BSTR)          // one matrix slot (elements)
#define STAGE (4*SLOT)           // Ah, Al, Bh, Bl
#define GEMM_SMEM (2*STAGE*2)    // bytes (double buffered) = 144KB
template<int EPI, int TERMS>
__global__ __launch_bounds__(256) void k_mma_gemm(
    const __nv_bfloat16* __restrict__ Ah, const __nv_bfloat16* __restrict__ Al,
    const __nv_bfloat16* __restrict__ Bh, const __nv_bfloat16* __restrict__ Bl,
    const float* __restrict__ bias, const float* __restrict__ R,
    float* __restrict__ C, __nv_bfloat16* __restrict__ C1, __nv_bfloat16* __restrict__ C2,
    int N, int K)
{
    extern __shared__ __align__(16) __nv_bfloat16 sm[];
    int tid = threadIdx.x;
    int warp = tid >> 5, lane = tid & 31;
    int wy = warp >> 2, wx = warp & 3;          // wy: M (0..1) x64, wx: N (0..3) x32
    int bm = blockIdx.x * 128, bn = blockIdx.y * 128;

    int sr = tid >> 3, seg = (tid & 7) * 8;     // staging coords

    float d[4][4][4];
    #pragma unroll
    for (int mt = 0; mt < 4; mt++)
        #pragma unroll
        for (int nt = 0; nt < 4; nt++)
            #pragma unroll
            for (int i = 0; i < 4; i++) d[mt][nt][i] = 0.f;

    const int NC = K / 64;

    // ---- stage chunk 0 ----
    {
        __nv_bfloat16* s = sm;
        #pragma unroll
        for (int p = 0; p < 4; p++){
            int row = p*32 + sr;
            size_t gro = (size_t)(bm + row)*K + seg;
            size_t grb = (size_t)(bn + row)*K + seg;
            cp16(smem_u32(&s[row*BSTR + seg]),          Ah + gro);
            cp16(smem_u32(&s[SLOT + row*BSTR + seg]),   Al + gro);
            cp16(smem_u32(&s[2*SLOT + row*BSTR + seg]), Bh + grb);
            if (TERMS == 3)
                cp16(smem_u32(&s[3*SLOT + row*BSTR + seg]), Bl + grb);
        }
        cp_commit();
    }

    for (int c = 0; c < NC; c++){
        if (c + 1 < NC){
            __nv_bfloat16* s = sm + ((c+1) & 1) * STAGE;
            int kc = (c+1) * 64;
            #pragma unroll
            for (int p = 0; p < 4; p++){
                int row = p*32 + sr;
                size_t gro = (size_t)(bm + row)*K + kc + seg;
                size_t grb = (size_t)(bn + row)*K + kc + seg;
                cp16(smem_u32(&s[row*BSTR + seg]),          Ah + gro);
                cp16(smem_u32(&s[SLOT + row*BSTR + seg]),   Al + gro);
                cp16(smem_u32(&s[2*SLOT + row*BSTR + seg]), Bh + grb);
                if (TERMS == 3)
                    cp16(smem_u32(&s[3*SLOT + row*BSTR + seg]), Bl + grb);
            }
            cp_commit();
            cp_wait<1>();
        } else {
            cp_wait<0>();
        }
        __syncthreads();

        __nv_bfloat16* sAh = sm + (c & 1) * STAGE;
        __nv_bfloat16* sAl = sAh + SLOT;
        __nv_bfloat16* sBh = sAh + 2*SLOT;
        __nv_bfloat16* sBl = sAh + 3*SLOT;

        #pragma unroll
        for (int ks = 0; ks < 4; ks++){
            uint32_t ah[4][4], al[4][4], bh[4][2], bl[4][2];
            #pragma unroll
            for (int mt = 0; mt < 4; mt++){
                int r = wy*64 + mt*16 + (lane & 15);
                int cc2 = ks*16 + (lane >> 4)*8;
                ldm_x4(ah[mt][0],ah[mt][1],ah[mt][2],ah[mt][3], smem_u32(&sAh[r*BSTR + cc2]));
                ldm_x4(al[mt][0],al[mt][1],al[mt][2],al[mt][3], smem_u32(&sAl[r*BSTR + cc2]));
            }
            #pragma unroll
            for (int nn = 0; nn < 2; nn++){
                int g8 = lane >> 3;
                int n = wx*32 + nn*16 + ((g8 >> 1) ? 8 : 0) + (lane & 7);
                int cc2 = ks*16 + (g8 & 1)*8;
                uint32_t r0,r1,r2,r3;
                ldm_x4(r0,r1,r2,r3, smem_u32(&sBh[n*BSTR + cc2]));
                bh[nn*2+0][0]=r0; bh[nn*2+0][1]=r1; bh[nn*2+1][0]=r2; bh[nn*2+1][1]=r3;
                if (TERMS == 3){
                    ldm_x4(r0,r1,r2,r3, smem_u32(&sBl[n*BSTR + cc2]));
                    bl[nn*2+0][0]=r0; bl[nn*2+0][1]=r1; bl[nn*2+1][0]=r2; bl[nn*2+1][1]=r3;
                }
            }
            #pragma unroll
            for (int mt = 0; mt < 4; mt++)
                #pragma unroll
                for (int nt = 0; nt < 4; nt++){
                    mma_bf16(d[mt][nt], ah[mt], bh[nt]);       // Ah*Bh
                    mma_bf16(d[mt][nt], al[mt], bh[nt]);       // Al*Bh
                    if (TERMS == 3)
                        mma_bf16(d[mt][nt], ah[mt], bl[nt]);   // Ah*Bl
                }
        }
        __syncthreads();
    }

    int g = lane >> 2, t = lane & 3;
    #pragma unroll
    for (int mt = 0; mt < 4; mt++){
        #pragma unroll
        for (int nt = 0; nt < 4; nt++){
            int c = bn + wx*32 + nt*8 + t*2;
            float b0 = bias[c], b1 = bias[c+1];
            #pragma unroll
            for (int hr = 0; hr < 2; hr++){
                int r = bm + wy*64 + mt*16 + g + hr*8;
                float v0 = d[mt][nt][hr*2+0] + b0;
                float v1 = d[mt][nt][hr*2+1] + b1;
                size_t go = (size_t)r * N + c;
                if (EPI == 0){
                    float2 o; o.x = v0; o.y = v1;
                    *(float2*)(C + go) = o;
                } else if (EPI == 1){
                    v0 = gelu_exact(v0); v1 = gelu_exact(v1);
                    __nv_bfloat16 h0,h1,l0,l1;
                    split_bf16(v0,h0,l0); split_bf16(v1,h1,l1);
                    *(__nv_bfloat162*)(C1 + go) = __nv_bfloat162(h0, h1);
                    *(__nv_bfloat162*)(C2 + go) = __nv_bfloat162(l0, l1);
                } else {
                    float2 rr = *(const float2*)(R + go);
                    float2 o; o.x = v0 + rr.x; o.y = v1 + rr.y;
                    *(float2*)(C + go) = o;
                }
            }
        }
    }
}

// ---------------- kernel 4: window means of q and k (256 thr) ----------------
__global__ __launch_bounds__(256) void k_winmean(const float* __restrict__ qkv,
                                                 float* __restrict__ qwin,
                                                 float* __restrict__ kwin){
    int bp = blockIdx.x; int b = bp / P2, p = bp - b*P2;
    int tid = threadIdx.x;
    int c = tid & 127, isK = tid >> 7;
    int hb = (p / NWIN) * WHS, wb = (p % NWIN) * WHS;
    const float* src = qkv + (isK ? QKC : 0) + c;
    float s = 0.f;
    #pragma unroll 8
    for (int r = 0; r < W2; r++){
        size_t tok = (size_t)(b*HH + hb + (r >> 3))*WWI + wb + (r & 7);
        s += src[tok*QKVC];
    }
    (isK ? kwin : qwin)[(size_t)bp*CC + c] = s * (1.f/64.f);
}

// ---------------- kernel 5: routing logits + top-4 ----------------
__global__ __launch_bounds__(64) void k_route(const float* __restrict__ qwin,
                                              const float* __restrict__ kwin,
                                              int* __restrict__ idx){
    __shared__ float qr[128];
    __shared__ float lg[49];
    int bp = blockIdx.x; int b = bp / P2;
    int t = threadIdx.x;
    qr[t]      = qwin[(size_t)bp*CC + t];
    qr[t + 64] = qwin[(size_t)bp*CC + 64 + t];
    __syncthreads();
    if (t < P2){
        const float* kr = kwin + (size_t)(b*P2 + t)*CC;
        float s = 0.f;
        #pragma unroll 8
        for (int c = 0; c < CC; c++) s += qr[c] * kr[c];
        lg[t] = s;
    }
    __syncthreads();
    if (t == 0){
        unsigned long long used = 0ull;
        for (int r = 0; r < TOPK; r++){
            float best = -1e30f; int bi = 0;
            for (int j = 0; j < P2; j++)
                if (!((used >> j) & 1ull) && lg[j] > best){ best = lg[j]; bi = j; }
            used |= 1ull << bi;
            idx[bp*TOPK + r] = bi;
        }
    }
}

// ---------------- kernel 6: HMMA flash attention ----------------
#define QSTR 136                 // bf16 row stride (272B), conflict-free ldmatrix
#define QSZ  (64*QSTR)
__global__ __launch_bounds__(256) void k_attn(const float* __restrict__ qkv,
                                              const int* __restrict__ idx,
                                              float* __restrict__ op){
    extern __shared__ __align__(16) __nv_bfloat16 sm[];
    __nv_bfloat16* sQh = sm;
    __nv_bfloat16* sQl = sm + QSZ;
    __nv_bfloat16* sKh = sm + 2*QSZ;
    __nv_bfloat16* sVh = sm + 3*QSZ;
    __nv_bfloat16* sVl = sm + 4*QSZ;

    int bp = blockIdx.x; int b = bp / P2, p = bp - b*P2;
    int tid = threadIdx.x;
    int warp = tid >> 5, lane = tid & 31;
    int h = warp >> 1, qh = warp & 1;
    int g = lane >> 2, t4 = lane & 3;
    int ro = lane & 7, grp = lane >> 3;
    int hb = (p / NWIN)*WHS, wb = (p % NWIN)*WHS;

    #pragma unroll
    for (int i = 0; i < 16; i++){
        int li = i*256 + tid;
        int r = li >> 6, c2 = (li & 63)*2;
        size_t tok = (size_t)(b*HH + hb + (r >> 3))*WWI + wb + (r & 7);
        float2 v = *(const float2*)(qkv + tok*QKVC + c2);
        v.x *= SCALE; v.y *= SCALE;
        __nv_bfloat16 h0,l0,h1,l1;
        split_bf16(v.x,h0,l0); split_bf16(v.y,h1,l1);
        *(__nv_bfloat162*)&sQh[r*QSTR + c2] = __nv_bfloat162(h0,h1);
        *(__nv_bfloat162*)&sQl[r*QSTR + c2] = __nv_bfloat162(l0,l1);
    }
    __syncthreads();

    uint32_t qah[2][2][4], qal[2][2][4];
    #pragma unroll
    for (int mt = 0; mt < 2; mt++)
        #pragma unroll
        for (int ks = 0; ks < 2; ks++){
            int row = qh*32 + mt*16 + (grp & 1)*8 + ro;
            int col = h*32 + ks*16 + (grp >> 1)*8;
            ldm_x4(qah[mt][ks][0],qah[mt][ks][1],qah[mt][ks][2],qah[mt][ks][3],
                   smem_u32(&sQh[row*QSTR + col]));
            ldm_x4(qal[mt][ks][0],qal[mt][ks][1],qal[mt][ks][2],qal[mt][ks][3],
                   smem_u32(&sQl[row*QSTR + col]));
        }

    float o[2][4][4];
    #pragma unroll
    for (int mt = 0; mt < 2; mt++)
        #pragma unroll
        for (int nt = 0; nt < 4; nt++)
            #pragma unroll
            for (int i = 0; i < 4; i++) o[mt][nt][i] = 0.f;
    float mst[2][2] = {{-1e30f,-1e30f},{-1e30f,-1e30f}};
    float lst[2][2] = {{0.f,0.f},{0.f,0.f}};

    for (int tt = 0; tt < TOPK; tt++){
        int wsel = idx[bp*TOPK + tt];
        int bh2 = (wsel / NWIN)*WHS, bw2 = (wsel % NWIN)*WHS;
        __syncthreads();
        #pragma unroll
        for (int i = 0; i < 32; i++){
            int li = i*256 + tid;
            int k = li >> 7, c2 = (li & 127)*2;
            size_t tok = (size_t)(b*HH + bh2 + (k >> 3))*WWI + bw2 + (k & 7);
            float2 v = *(const float2*)(qkv + tok*QKVC + QKC + c2);
            if (c2 < 128){
                *(__nv_bfloat162*)&sKh[k*QSTR + c2] =
                    __nv_bfloat162(__float2bfloat16(v.x), __float2bfloat16(v.y));
            } else {
                int cv = c2 - 128;
                __nv_bfloat16 h0,l0,h1,l1;
                split_bf16(v.x,h0,l0); split_bf16(v.y,h1,l1);
                *(__nv_bfloat162*)&sVh[k*QSTR + cv] = __nv_bfloat162(h0,h1);
                *(__nv_bfloat162*)&sVl[k*QSTR + cv] = __nv_bfloat162(l0,l1);
            }
        }
        __syncthreads();

        float s[2][8][4];
        #pragma unroll
        for (int mt = 0; mt < 2; mt++)
            #pragma unroll
            for (int nt = 0; nt < 8; nt++)
                #pragma unroll
                for (int i = 0; i < 4; i++) s[mt][nt][i] = 0.f;
        #pragma unroll
        for (int ks = 0; ks < 2; ks++){
            uint32_t kb[8][2];
            int col = h*32 + ks*16 + (grp & 1)*8;
            #pragma unroll
            for (int j = 0; j < 4; j++){
                int row = j*16 + (grp >> 1)*8 + ro;
                uint32_t r0,r1,r2,r3;
                ldm_x4(r0,r1,r2,r3, smem_u32(&sKh[row*QSTR + col]));
                kb[2*j][0]=r0; kb[2*j][1]=r1; kb[2*j+1][0]=r2; kb[2*j+1][1]=r3;
            }
            #pragma unroll
            for (int mt = 0; mt < 2; mt++)
                #pragma unroll
                for (int nt = 0; nt < 8; nt++){
                    mma_bf16(s[mt][nt], qah[mt][ks], kb[nt]);
                    mma_bf16(s[mt][nt], qal[mt][ks], kb[nt]);
                }
        }

        uint32_t pa[2][4][4];
        #pragma unroll
        for (int mt = 0; mt < 2; mt++){
            float r0 = -1e30f, r1 = -1e30f;
            #pragma unroll
            for (int nt = 0; nt < 8; nt++){
                r0 = fmaxf(r0, fmaxf(s[mt][nt][0], s[mt][nt][1]));
                r1 = fmaxf(r1, fmaxf(s[mt][nt][2], s[mt][nt][3]));
            }
            r0 = fmaxf(r0, __shfl_xor_sync(0xffffffffu, r0, 1));
            r0 = fmaxf(r0, __shfl_xor_sync(0xffffffffu, r0, 2));
            r1 = fmaxf(r1, __shfl_xor_sync(0xffffffffu, r1, 1));
            r1 = fmaxf(r1, __shfl_xor_sync(0xffffffffu, r1, 2));
            float mn0 = fmaxf(mst[mt][0], r0), mn1 = fmaxf(mst[mt][1], r1);
            float c0 = __expf(mst[mt][0] - mn0), c1 = __expf(mst[mt][1] - mn1);
            mst[mt][0] = mn0; mst[mt][1] = mn1;
            float ls0 = 0.f, ls1 = 0.f;
            #pragma unroll
            for (int nt = 0; nt < 8; nt++){
                float e0 = __expf(s[mt][nt][0] - mn0);
                float e1 = __expf(s[mt][nt][1] - mn0);
                float e2 = __expf(s[mt][nt][2] - mn1);
                float e3 = __expf(s[mt][nt][3] - mn1);
                ls0 += e0 + e1; ls1 += e2 + e3;
                s[mt][nt][0] = e0; s[mt][nt][1] = e1;
                s[mt][nt][2] = e2; s[mt][nt][3] = e3;
            }
            ls0 += __shfl_xor_sync(0xffffffffu, ls0, 1);
            ls0 += __shfl_xor_sync(0xffffffffu, ls0, 2);
            ls1 += __shfl_xor_sync(0xffffffffu, ls1, 1);
            ls1 += __shfl_xor_sync(0xffffffffu, ls1, 2);
            lst[mt][0] = lst[mt][0]*c0 + ls0;
            lst[mt][1] = lst[mt][1]*c1 + ls1;
            #pragma unroll
            for (int nt = 0; nt < 4; nt++){
                o[mt][nt][0] *= c0; o[mt][nt][1] *= c0;
                o[mt][nt][2] *= c1; o[mt][nt][3] *= c1;
            }
            #pragma unroll
            for (int k2 = 0; k2 < 4; k2++){
                pa[mt][k2][0] = packbf2(s[mt][2*k2][0],   s[mt][2*k2][1]);
                pa[mt][k2][1] = packbf2(s[mt][2*k2][2],   s[mt][2*k2][3]);
                pa[mt][k2][2] = packbf2(s[mt][2*k2+1][0], s[mt][2*k2+1][1]);
                pa[mt][k2][3] = packbf2(s[mt][2*k2+1][2], s[mt][2*k2+1][3]);
            }
        }

        #pragma unroll
        for (int k2 = 0; k2 < 4; k2++){
            uint32_t vbh[4][2], vbl[4][2];
            int row = k2*16 + (grp & 1)*8 + ro;
            #pragma unroll
            for (int np = 0; np < 2; np++){
                int col = h*32 + np*16 + (grp >> 1)*8;
                uint32_t r0,r1,r2,r3;
                ldm_x4_t(r0,r1,r2,r3, smem_u32(&sVh[row*QSTR + col]));
                vbh[2*np][0]=r0; vbh[2*np][1]=r1; vbh[2*np+1][0]=r2; vbh[2*np+1][1]=r3;
                ldm_x4_t(r0,r1,r2,r3, smem_u32(&sVl[row*QSTR + col]));
                vbl[2*np][0]=r0; vbl[2*np][1]=r1; vbl[2*np+1][0]=r2; vbl[2*np+1][1]=r3;
            }
            #pragma unroll
            for (int mt = 0; mt < 2; mt++)
                #pragma unroll
                for (int nt = 0; nt < 4; nt++){
                    mma_bf16(o[mt][nt], pa[mt][k2], vbh[nt]);
                    mma_bf16(o[mt][nt], pa[mt][k2], vbl[nt]);
                }
        }
    }

    #pragma unroll
    for (int mt = 0; mt < 2; mt++){
        float inv0 = 1.f / lst[mt][0], inv1 = 1.f / lst[mt][1];
        int r0 = qh*32 + mt*16 + g, r1 = r0 + 8;
        size_t tok0 = (size_t)(b*HH + hb + (r0 >> 3))*WWI + wb + (r0 & 7);
        size_t tok1 = (size_t)(b*HH + hb + (r1 >> 3))*WWI + wb + (r1 & 7);
        #pragma unroll
        for (int nt = 0; nt < 4; nt++){
            int col = h*32 + nt*8 + t4*2;
            float2 v0; v0.x = o[mt][nt][0]*inv0; v0.y = o[mt][nt][1]*inv0;
            float2 v1; v1.x = o[mt][nt][2]*inv1; v1.y = o[mt][nt][3]*inv1;
            *(float2*)(op + tok0*CC + col) = v0;
            *(float2*)(op + tok1*CC + col) = v1;
        }
    }
}
#define ATTN_SMEM (5*QSZ*2)

// ---------------- kernel 7: LEPE 5x5 dwconv on v, add att, write split bf16 ----------------
__global__ __launch_bounds__(256) void k_lepe(const float* __restrict__ qkv,
                                              const float* __restrict__ lw,
                                              const float* __restrict__ lb,
                                              const float* __restrict__ att,
                                              __nv_bfloat16* __restrict__ oh,
                                              __nv_bfloat16* __restrict__ ol){
    __shared__ __align__(16) float s[5*32*57];
    int bh = blockIdx.x; int b = bh / HH, h = bh % HH;
    int c0 = blockIdx.y * 32;
    int tid = threadIdx.x;
    for (int l = tid; l < 5*32*56; l += 256){
        int row = l / (32*56);
        int rem = l - row*(32*56);
        int wv  = rem >> 5;
        int c   = rem & 31;
        int hr  = h + row - 2;
        float v = 0.f;
        if (hr >= 0 && hr < HH)
            v = qkv[((size_t)((b*HH + hr)*WWI + wv))*QKVC + 2*QKC + c0 + c];
        s[row*32*57 + c*57 + wv] = v;
    }
    __syncthreads();
    int c = tid & 31;
    float wg[25];
    #pragma unroll
    for (int t = 0; t < 25; t++) wg[t] = lw[(c0 + c)*25 + t];
    float bias = lb[c0 + c];
    for (int l = tid; l < 56*32; l += 256){
        int w = l >> 5;
        float acc = bias;
        #pragma unroll
        for (int ky = 0; ky < 5; ky++){
            const float* srow = &s[ky*32*57 + c*57];
            #pragma unroll
            for (int kx = 0; kx < 5; kx++){
                int ww = w + kx - 2;
                if (ww >= 0 && ww < WWI) acc += wg[ky*5+kx] * srow[ww];
            }
        }
        size_t go = ((size_t)((b*HH + h)*WWI + w))*CC + c0 + c;
        float v = att[go] + acc;
        __nv_bfloat16 hh, ll; split_bf16(v, hh, ll);
        oh[go] = hh; ol[go] = ll;
    }
}

// ---------------- kernel 8: NHWC -> NCHW ----------------
__global__ void k_tr(const float* __restrict__ in, float* __restrict__ out){
    __shared__ float t[32][33];
    int b = blockIdx.z, c0 = blockIdx.y*32, p0 = blockIdx.x*32;
    int tx = threadIdx.x, ty = threadIdx.y;
    #pragma unroll
    for (int u = 0; u < 4; u++)
        t[ty + u*8][tx] = in[((size_t)(b*(HH*WWI) + p0 + ty + u*8))*CC + c0 + tx];
    __syncthreads();
    #pragma unroll
    for (int u = 0; u < 4; u++)
        out[((size_t)(b*CC + c0 + ty + u*8))*(HH*WWI) + p0 + tx] = t[tx][ty + u*8];
}

// ---------------- launcher ----------------
extern "C" void kernel_launch(void* const* d_in, const int* in_sizes, int n_in,
                              void* d_out, int out_size){
    const float* x      = (const float*)d_in[0];
    const float* pos_w  = (const float*)d_in[1];
    const float* pos_b  = (const float*)d_in[2];
    const float* ln1_g  = (const float*)d_in[3];
    const float* ln1_b  = (const float*)d_in[4];
    const float* qkv_w  = (const float*)d_in[5];
    const float* qkv_b  = (const float*)d_in[6];
    const float* lepe_w = (const float*)d_in[7];
    const float* lepe_b = (const float*)d_in[8];
    const float* wo_w   = (const float*)d_in[9];
    const float* wo_b   = (const float*)d_in[10];
    const float* ln2_g  = (const float*)d_in[11];
    const float* ln2_b  = (const float*)d_in[12];
    const float* mlp_w1 = (const float*)d_in[13];
    const float* mlp_b1 = (const float*)d_in[14];
    const float* mlp_w2 = (const float*)d_in[15];
    const float* mlp_b2 = (const float*)d_in[16];
    float* out = (float*)d_out;

    float *p_xh, *p_qkv, *p_att, *p_qwin, *p_kwin;
    int *p_idx;
    __nv_bfloat16 *p_yh, *p_yl, *p_ath, *p_atl, *p_h1h, *p_h1l;
    __nv_bfloat16 *p_wqh, *p_wql, *p_woh, *p_wol, *p_w1h, *p_w1l, *p_w2h, *p_w2l;
    cudaGetSymbolAddress((void**)&p_xh,  g_xh);
    cudaGetSymbolAddress((void**)&p_qkv, g_qkv);
    cudaGetSymbolAddress((void**)&p_att, g_att);
    cudaGetSymbolAddress((void**)&p_qwin,g_qwin);
    cudaGetSymbolAddress((void**)&p_kwin,g_kwin);
    cudaGetSymbolAddress((void**)&p_idx, g_idx);
    cudaGetSymbolAddress((void**)&p_yh,  g_yh);
    cudaGetSymbolAddress((void**)&p_yl,  g_yl);
    cudaGetSymbolAddress((void**)&p_ath, g_ath);
    cudaGetSymbolAddress((void**)&p_atl, g_atl);
    cudaGetSymbolAddress((void**)&p_h1h, g_h1h);
    cudaGetSymbolAddress((void**)&p_h1l, g_h1l);
    cudaGetSymbolAddress((void**)&p_wqh, g_wqh);
    cudaGetSymbolAddress((void**)&p_wql, g_wql);
    cudaGetSymbolAddress((void**)&p_woh, g_woh);
    cudaGetSymbolAddress((void**)&p_wol, g_wol);
    cudaGetSymbolAddress((void**)&p_w1h, g_w1h);
    cudaGetSymbolAddress((void**)&p_w1l, g_w1l);
    cudaGetSymbolAddress((void**)&p_w2h, g_w2h);
    cudaGetSymbolAddress((void**)&p_w2l, g_w2l);

    cudaFuncSetAttribute(k_mma_gemm<0,3>, cudaFuncAttributeMaxDynamicSharedMemorySize, GEMM_SMEM);
    cudaFuncSetAttribute(k_mma_gemm<1,2>, cudaFuncAttributeMaxDynamicSharedMemorySize, GEMM_SMEM);
    cudaFuncSetAttribute(k_mma_gemm<2,2>, cudaFuncAttributeMaxDynamicSharedMemorySize, GEMM_SMEM);
    cudaFuncSetAttribute(k_attn, cudaFuncAttributeMaxDynamicSharedMemorySize, ATTN_SMEM);

    // 1. pos dwconv + residual -> xh (NHWC)
    k_posconv<<<dim3(BB*HH, 2), 256>>>(x, pos_w, pos_b, p_xh);
    // 2. LN1 -> split bf16 y
    k_ln<<<TOK/8, 256>>>(p_xh, ln1_g, ln1_b, p_yh, p_yl);
    // 3. fused weight transpose + split
    k_wsplit_all<<<640, 256>>>(qkv_w, wo_w, mlp_w1, mlp_w2,
                               p_wqh, p_wql, p_woh, p_wol,
                               p_w1h, p_w1l, p_w2h, p_w2l);
    // 4. QKV gemm -> qkv fp32 (3-term)   [profiled launch]
    k_mma_gemm<0,3><<<dim3(TOK/128, QKVC/128), 256, GEMM_SMEM>>>(
        p_yh, p_yl, p_wqh, p_wql, qkv_b, nullptr, p_qkv, nullptr, nullptr, QKVC, CC);
    // 5. window means
    k_winmean<<<BB*P2, 256>>>(p_qkv, p_qwin, p_kwin);
    // 6. routing top-4
    k_route<<<BB*P2, 64>>>(p_qwin, p_kwin, p_idx);
    // 7. HMMA attention -> att fp32 (NHWC)
    k_attn<<<BB*P2, 256, ATTN_SMEM>>>(p_qkv, p_idx, p_att);
    // 8. lepe: att + dwconv5x5(v) -> split bf16
    k_lepe<<<dim3(BB*HH, 4), 256>>>(p_qkv, lepe_w, lepe_b, p_att, p_ath, p_atl);
    // 9. wo gemm with residual (2-term): xh = xh + (att+lepe) @ wo + b
    k_mma_gemm<2,2><<<dim3(TOK/128, CC/128), 256, GEMM_SMEM>>>(
        p_ath, p_atl, p_woh, p_wol, wo_b, p_xh, p_xh, nullptr, nullptr, CC, CC);
    // 10. LN2 -> split bf16 y
    k_ln<<<TOK/8, 256>>>(p_xh, ln2_g, ln2_b, p_yh, p_yl);
    // 11. mlp1 + gelu (2-term) -> split bf16 h1
    k_mma_gemm<1,2><<<dim3(TOK/128, 3*CC/128), 256, GEMM_SMEM>>>(
        p_yh, p_yl, p_w1h, p_w1l, mlp_b1, nullptr, nullptr, p_h1h, p_h1l, 3*CC, CC);
    // 12. mlp2 with residual (2-term): xh = xh + h1 @ w2 + b
    k_mma_gemm<2,2><<<dim3(TOK/128, CC/128), 256, GEMM_SMEM>>>(
        p_h1h, p_h1l, p_w2h, p_w2l, mlp_b2, p_xh, p_xh, nullptr, nullptr, CC, 3*CC);
    // 13. NHWC -> NCHW
    k_tr<<<dim3((HH*WWI)/32, CC/32, BB), dim3(32, 8)>>>(p_xh, out);
}

// round 12
// speedup vs baseline: 1.1804x; 1.1804x over previous
#include <cuda_runtime.h>
#include <cuda_bf16.h>
#include <cstdint>

#define BB 16
#define CC 128
#define HH 56
#define WWI 56
#define TOK (BB*HH*WWI)          // 50176
#define QKC 128
#define QKVC 384
#define NWIN 7
#define WHS 8
#define P2 49
#define W2 64
#define TOPK 4
#define HEADS 4
#define HD 32
#define SCALE 0.08838834764831845f

typedef unsigned long long ull;

// ---------------- scratch (device globals; no allocation) ----------------
__device__ float g_xh [TOK*CC];
__device__ float g_qkv[TOK*QKVC];
__device__ float g_att[TOK*CC];
__device__ float g_qwin[BB*P2*CC];
__device__ float g_kwin[BB*P2*CC];
__device__ int   g_idx [BB*P2*TOPK];
// split-bf16 activations
__device__ __nv_bfloat16 g_yh [TOK*CC],  g_yl [TOK*CC];
__device__ __nv_bfloat16 g_ath[TOK*CC];
__device__ __nv_bfloat16 g_h1h[TOK*3*CC];
// split-bf16 weights, transposed to [N,K]
__device__ __nv_bfloat16 g_wqh[QKVC*CC], g_wql[QKVC*CC];
__device__ __nv_bfloat16 g_woh[CC*CC];
__device__ __nv_bfloat16 g_w1h[3*CC*CC];
__device__ __nv_bfloat16 g_w2h[CC*3*CC];

// ---------------- helpers ----------------
__device__ __forceinline__ uint32_t smem_u32(const void* p){
    uint32_t a;
    asm("{ .reg .u64 t; cvta.to.shared.u64 t, %1; cvt.u32.u64 %0, t; }" : "=r"(a) : "l"(p));
    return a;
}
__device__ __forceinline__ void ldm_x4(uint32_t& r0,uint32_t& r1,uint32_t& r2,uint32_t& r3, uint32_t addr){
    asm volatile("ldmatrix.sync.aligned.m8n8.x4.shared.b16 {%0,%1,%2,%3}, [%4];"
        : "=r"(r0),"=r"(r1),"=r"(r2),"=r"(r3) : "r"(addr));
}
__device__ __forceinline__ void ldm_x4_t(uint32_t& r0,uint32_t& r1,uint32_t& r2,uint32_t& r3, uint32_t addr){
    asm volatile("ldmatrix.sync.aligned.m8n8.x4.trans.shared.b16 {%0,%1,%2,%3}, [%4];"
        : "=r"(r0),"=r"(r1),"=r"(r2),"=r"(r3) : "r"(addr));
}
__device__ __forceinline__ void mma_bf16(float* d, const uint32_t* a, const uint32_t* b){
    asm volatile("mma.sync.aligned.m16n8k16.row.col.f32.bf16.bf16.f32 "
        "{%0,%1,%2,%3}, {%4,%5,%6,%7}, {%8,%9}, {%0,%1,%2,%3};"
        : "+f"(d[0]),"+f"(d[1]),"+f"(d[2]),"+f"(d[3])
        : "r"(a[0]),"r"(a[1]),"r"(a[2]),"r"(a[3]), "r"(b[0]),"r"(b[1]));
}
__device__ __forceinline__ uint32_t packbf2(float lo, float hi){
    uint32_t r;
    asm("cvt.rn.bf16x2.f32 %0, %1, %2;" : "=r"(r) : "f"(hi), "f"(lo));
    return r;
}
__device__ __forceinline__ float gelu_exact(float v){
    return 0.5f * v * (1.0f + erff(v * 0.70710678118654752f));
}
__device__ __forceinline__ void split_bf16(float v, __nv_bfloat16& h, __nv_bfloat16& l){
    h = __float2bfloat16(v);
    l = __float2bfloat16(v - __bfloat162float(h));
}

// ---------------- fused weight transpose + split (one launch) ----------------
// QKV gets hi+lo; Wo/MLP1/MLP2 get hi only (1-term GEMMs).
__global__ __launch_bounds__(256) void k_wsplit_all(
    const float* __restrict__ qkv_w, const float* __restrict__ wo_w,
    const float* __restrict__ mlp_w1, const float* __restrict__ mlp_w2,
    __nv_bfloat16* __restrict__ wqh, __nv_bfloat16* __restrict__ wql,
    __nv_bfloat16* __restrict__ woh,
    __nv_bfloat16* __restrict__ w1h,
    __nv_bfloat16* __restrict__ w2h)
{
    int blk = blockIdx.x;
    const float* src; __nv_bfloat16 *dh, *dl; int K, N, base;
    if (blk < 192)      { src = qkv_w;  dh = wqh; dl = wql;     K = CC;   N = QKVC; base = 0;   }
    else if (blk < 256) { src = wo_w;   dh = woh; dl = nullptr; K = CC;   N = CC;   base = 192; }
    else if (blk < 448) { src = mlp_w1; dh = w1h; dl = nullptr; K = CC;   N = 3*CC; base = 256; }
    else                { src = mlp_w2; dh = w2h; dl = nullptr; K = 3*CC; N = CC;   base = 448; }
    int i = (blk - base) * 256 + threadIdx.x;
    if (i >= N * K) return;
    int n = i / K, k = i - n * K;
    float v = src[(size_t)k * N + n];
    __nv_bfloat16 h, l; split_bf16(v, h, l);
    dh[i] = h;
    if (dl) dl[i] = l;
}

// ---------------- kernel 1: x + dwconv3x3(x) -> xh (NHWC) ----------------
__global__ __launch_bounds__(256) void k_posconv(const float* __restrict__ x,
                                                 const float* __restrict__ pw,
                                                 const float* __restrict__ pb,
                                                 float* __restrict__ xh){
    __shared__ __align__(16) float s[3*64*57];
    int bh = blockIdx.x; int b = bh / HH, h = bh % HH;
    int c0 = blockIdx.y * 64;
    int tid = threadIdx.x;
    for (int l = tid; l < 3*64*56; l += 256){
        int row = l / (64*56);
        int rem = l - row*(64*56);
        int c   = rem / 56;
        int wv  = rem - c*56;
        int hr  = h + row - 1;
        float v = 0.f;
        if (hr >= 0 && hr < HH)
            v = x[((size_t)((b*CC + c0 + c)*HH + hr))*WWI + wv];
        s[row*64*57 + c*57 + wv] = v;
    }
    __syncthreads();
    int c = tid & 63;
    float wgt[9];
    #pragma unroll
    for (int t = 0; t < 9; t++) wgt[t] = pw[(c0 + c)*9 + t];
    float bias = pb[c0 + c];
    for (int l = tid; l < 56*64; l += 256){
        int w = l >> 6;
        float acc = bias;
        #pragma unroll
        for (int ky = 0; ky < 3; ky++){
            const float* srow = &s[ky*64*57 + c*57];
            #pragma unroll
            for (int kx = 0; kx < 3; kx++){
                int ww = w + kx - 1;
                if (ww >= 0 && ww < WWI) acc += wgt[ky*3+kx] * srow[ww];
            }
        }
        acc += s[1*64*57 + c*57 + w];   // residual (center x)
        xh[((size_t)((b*HH + h)*WWI + w))*CC + c0 + c] = acc;
    }
}

// ---------------- kernel 2: LayerNorm over C -> bf16 (lo optional) ----------------
__global__ __launch_bounds__(256) void k_ln(const float* __restrict__ in,
                                            const float* __restrict__ g,
                                            const float* __restrict__ bt,
                                            __nv_bfloat16* __restrict__ oh,
                                            __nv_bfloat16* __restrict__ ol){
    int warp = threadIdx.x >> 5, lane = threadIdx.x & 31;
    int tok = blockIdx.x * 8 + warp;
    const float4* ip = (const float4*)(in + (size_t)tok * CC);
    float4 v = ip[lane];
    float s = v.x + v.y + v.z + v.w;
    float q = v.x*v.x + v.y*v.y + v.z*v.z + v.w*v.w;
    #pragma unroll
    for (int o = 16; o; o >>= 1){
        s += __shfl_xor_sync(0xffffffffu, s, o);
        q += __shfl_xor_sync(0xffffffffu, q, o);
    }
    float m   = s * (1.f/128.f);
    float var = q * (1.f/128.f) - m*m;
    float r   = rsqrtf(var + 1e-6f);
    float4 gg = ((const float4*)g)[lane];
    float4 bb = ((const float4*)bt)[lane];
    float o0 = (v.x - m)*r*gg.x + bb.x;
    float o1 = (v.y - m)*r*gg.y + bb.y;
    float o2 = (v.z - m)*r*gg.z + bb.z;
    float o3 = (v.w - m)*r*gg.w + bb.w;
    __nv_bfloat16 h0,h1,h2,h3,l0,l1,l2,l3;
    split_bf16(o0,h0,l0); split_bf16(o1,h1,l1); split_bf16(o2,h2,l2); split_bf16(o3,h3,l3);
    size_t off = (size_t)tok * CC + lane*4;
    *(__nv_bfloat162*)(oh + off)     = __nv_bfloat162(h0, h1);
    *(__nv_bfloat162*)(oh + off + 2) = __nv_bfloat162(h2, h3);
    if (ol){
        *(__nv_bfloat162*)(ol + off)     = __nv_bfloat162(l0, l1);
        *(__nv_bfloat162*)(ol + off + 2) = __nv_bfloat162(l2, l3);
    }
}

// ---------------- HMMA GEMM: C[M,N] = A[M,K] @ W (R5-proven 128x64 tile) ----------------
// A: hi(/lo) bf16 [M,K] row-major. B: hi(/lo) bf16 [N,K] row-major.
// TERMS: 3 = Ah*Bh + Al*Bh + Ah*Bl ; 1 = Ah*Bh
// EPI: 0 = bias -> fp32 C ; 1 = bias+GELU -> bf16 C1 (C2 lo optional) ; 2 = bias+residual R -> fp32 C
#define ASTR 72   // smem row stride in bf16 (144B: conflict-free ldmatrix)
template<int EPI, int TERMS>
__global__ __launch_bounds__(256) void k_mma_gemm(
    const __nv_bfloat16* __restrict__ Ah, const __nv_bfloat16* __restrict__ Al,
    const __nv_bfloat16* __restrict__ Bh, const __nv_bfloat16* __restrict__ Bl,
    const float* __restrict__ bias, const float* __restrict__ R,
    float* __restrict__ C, __nv_bfloat16* __restrict__ C1, __nv_bfloat16* __restrict__ C2,
    int N, int K)
{
    extern __shared__ __align__(16) __nv_bfloat16 sm[];
    __nv_bfloat16* sAh = sm;                    // 128 x ASTR
    __nv_bfloat16* sAl = sm + 128*ASTR;         // 128 x ASTR (TERMS==3)
    __nv_bfloat16* sBh = sm + 2*128*ASTR;       // 64 x ASTR
    __nv_bfloat16* sBl = sm + 2*128*ASTR + 64*ASTR;

    int tid = threadIdx.x;
    int warp = tid >> 5, lane = tid & 31;
    int wy = warp >> 1, wx = warp & 1;          // wy: M (0..3), wx: N (0..1)
    int bm = blockIdx.x * 128, bn = blockIdx.y * 64;

    float d[2][4][4];
    #pragma unroll
    for (int mt = 0; mt < 2; mt++)
        #pragma unroll
        for (int nt = 0; nt < 4; nt++)
            #pragma unroll
            for (int i = 0; i < 4; i++) d[mt][nt][i] = 0.f;

    int lr = tid >> 3;          // 0..31
    int lc = (tid & 7) * 8;     // 0..56

    for (int kc = 0; kc < K; kc += 64){
        if (kc) __syncthreads();
        #pragma unroll
        for (int p = 0; p < 4; p++){
            int row = p*32 + lr;
            *(uint4*)&sAh[row*ASTR + lc] = *(const uint4*)(Ah + (size_t)(bm+row)*K + kc + lc);
            if (TERMS == 3)
                *(uint4*)&sAl[row*ASTR + lc] = *(const uint4*)(Al + (size_t)(bm+row)*K + kc + lc);
        }
        #pragma unroll
        for (int p = 0; p < 2; p++){
            int row = p*32 + lr;
            *(uint4*)&sBh[row*ASTR + lc] = *(const uint4*)(Bh + (size_t)(bn+row)*K + kc + lc);
            if (TERMS == 3)
                *(uint4*)&sBl[row*ASTR + lc] = *(const uint4*)(Bl + (size_t)(bn+row)*K + kc + lc);
        }
        __syncthreads();
        #pragma unroll
        for (int ks = 0; ks < 4; ks++){
            uint32_t ah[2][4], al[2][4], bh[4][2], bl[4][2];
            #pragma unroll
            for (int mt = 0; mt < 2; mt++){
                int r = wy*32 + mt*16 + (lane & 15);
                int c = ks*16 + (lane >> 4)*8;
                ldm_x4(ah[mt][0],ah[mt][1],ah[mt][2],ah[mt][3], smem_u32(&sAh[r*ASTR + c]));
                if (TERMS == 3)
                    ldm_x4(al[mt][0],al[mt][1],al[mt][2],al[mt][3], smem_u32(&sAl[r*ASTR + c]));
            }
            #pragma unroll
            for (int nn = 0; nn < 2; nn++){
                int g8 = lane >> 3;
                int n = wx*32 + nn*16 + ((g8 >> 1) ? 8 : 0) + (lane & 7);
                int c = ks*16 + (g8 & 1)*8;
                uint32_t r0,r1,r2,r3;
                ldm_x4(r0,r1,r2,r3, smem_u32(&sBh[n*ASTR + c]));
                bh[nn*2+0][0]=r0; bh[nn*2+0][1]=r1; bh[nn*2+1][0]=r2; bh[nn*2+1][1]=r3;
                if (TERMS == 3){
                    ldm_x4(r0,r1,r2,r3, smem_u32(&sBl[n*ASTR + c]));
                    bl[nn*2+0][0]=r0; bl[nn*2+0][1]=r1; bl[nn*2+1][0]=r2; bl[nn*2+1][1]=r3;
                }
            }
            #pragma unroll
            for (int mt = 0; mt < 2; mt++)
                #pragma unroll
                for (int nt = 0; nt < 4; nt++){
                    mma_bf16(d[mt][nt], ah[mt], bh[nt]);       // Ah*Bh
                    if (TERMS == 3){
                        mma_bf16(d[mt][nt], al[mt], bh[nt]);   // Al*Bh
                        mma_bf16(d[mt][nt], ah[mt], bl[nt]);   // Ah*Bl
                    }
                }
        }
    }

    int g = lane >> 2, t = lane & 3;
    #pragma unroll
    for (int mt = 0; mt < 2; mt++){
        #pragma unroll
        for (int nt = 0; nt < 4; nt++){
            int c = bn + wx*32 + nt*8 + t*2;
            float b0 = bias[c], b1 = bias[c+1];
            #pragma unroll
            for (int hr = 0; hr < 2; hr++){
                int r = bm + wy*32 + mt*16 + g + hr*8;
                float v0 = d[mt][nt][hr*2+0] + b0;
                float v1 = d[mt][nt][hr*2+1] + b1;
                size_t go = (size_t)r * N + c;
                if (EPI == 0){
                    float2 o; o.x = v0; o.y = v1;
                    *(float2*)(C + go) = o;
                } else if (EPI == 1){
                    v0 = gelu_exact(v0); v1 = gelu_exact(v1);
                    __nv_bfloat16 h0,h1,l0,l1;
                    split_bf16(v0,h0,l0); split_bf16(v1,h1,l1);
                    *(__nv_bfloat162*)(C1 + go) = __nv_bfloat162(h0, h1);
                    if (C2) *(__nv_bfloat162*)(C2 + go) = __nv_bfloat162(l0, l1);
                } else {
                    float2 rr = *(const float2*)(R + go);
                    float2 o; o.x = v0 + rr.x; o.y = v1 + rr.y;
                    *(float2*)(C + go) = o;
                }
            }
        }
    }
}
#define GEMM_SMEM ((2*128*ASTR + 2*64*ASTR) * 2)

// ---------------- kernel 4: window means of q and k (256 thr) ----------------
__global__ __launch_bounds__(256) void k_winmean(const float* __restrict__ qkv,
                                                 float* __restrict__ qwin,
                                                 float* __restrict__ kwin){
    int bp = blockIdx.x; int b = bp / P2, p = bp - b*P2;
    int tid = threadIdx.x;
    int c = tid & 127, isK = tid >> 7;
    int hb = (p / NWIN) * WHS, wb = (p % NWIN) * WHS;
    const float* src = qkv + (isK ? QKC : 0) + c;
    float s = 0.f;
    #pragma unroll 8
    for (int r = 0; r < W2; r++){
        size_t tok = (size_t)(b*HH + hb + (r >> 3))*WWI + wb + (r & 7);
        s += src[tok*QKVC];
    }
    (isK ? kwin : qwin)[(size_t)bp*CC + c] = s * (1.f/64.f);
}

// ---------------- kernel 5: routing logits + top-4 ----------------
__global__ __launch_bounds__(64) void k_route(const float* __restrict__ qwin,
                                              const float* __restrict__ kwin,
                                              int* __restrict__ idx){
    __shared__ float qr[128];
    __shared__ float lg[49];
    int bp = blockIdx.x; int b = bp / P2;
    int t = threadIdx.x;
    qr[t]      = qwin[(size_t)bp*CC + t];
    qr[t + 64] = qwin[(size_t)bp*CC + 64 + t];
    __syncthreads();
    if (t < P2){
        const float* kr = kwin + (size_t)(b*P2 + t)*CC;
        float s = 0.f;
        #pragma unroll 8
        for (int c = 0; c < CC; c++) s += qr[c] * kr[c];
        lg[t] = s;
    }
    __syncthreads();
    if (t == 0){
        unsigned long long used = 0ull;
        for (int r = 0; r < TOPK; r++){
            float best = -1e30f; int bi = 0;
            for (int j = 0; j < P2; j++)
                if (!((used >> j) & 1ull) && lg[j] > best){ best = lg[j]; bi = j; }
            used |= 1ull << bi;
            idx[bp*TOPK + r] = bi;
        }
    }
}

// ---------------- kernel 6: HMMA flash attention ----------------
#define QSTR 136                 // bf16 row stride (272B), conflict-free ldmatrix
#define QSZ  (64*QSTR)
__global__ __launch_bounds__(256) void k_attn(const float* __restrict__ qkv,
                                              const int* __restrict__ idx,
                                              float* __restrict__ op){
    extern __shared__ __align__(16) __nv_bfloat16 sm[];
    __nv_bfloat16* sQh = sm;
    __nv_bfloat16* sQl = sm + QSZ;
    __nv_bfloat16* sKh = sm + 2*QSZ;
    __nv_bfloat16* sVh = sm + 3*QSZ;
    __nv_bfloat16* sVl = sm + 4*QSZ;

    int bp = blockIdx.x; int b = bp / P2, p = bp - b*P2;
    int tid = threadIdx.x;
    int warp = tid >> 5, lane = tid & 31;
    int h = warp >> 1, qh = warp & 1;
    int g = lane >> 2, t4 = lane & 3;
    int ro = lane & 7, grp = lane >> 3;
    int hb = (p / NWIN)*WHS, wb = (p % NWIN)*WHS;

    #pragma unroll
    for (int i = 0; i < 16; i++){
        int li = i*256 + tid;
        int r = li >> 6, c2 = (li & 63)*2;
        size_t tok = (size_t)(b*HH + hb + (r >> 3))*WWI + wb + (r & 7);
        float2 v = *(const float2*)(qkv + tok*QKVC + c2);
        v.x *= SCALE; v.y *= SCALE;
        __nv_bfloat16 h0,l0,h1,l1;
        split_bf16(v.x,h0,l0); split_bf16(v.y,h1,l1);
        *(__nv_bfloat162*)&sQh[r*QSTR + c2] = __nv_bfloat162(h0,h1);
        *(__nv_bfloat162*)&sQl[r*QSTR + c2] = __nv_bfloat162(l0,l1);
    }
    __syncthreads();

    uint32_t qah[2][2][4], qal[2][2][4];
    #pragma unroll
    for (int mt = 0; mt < 2; mt++)
        #pragma unroll
        for (int ks = 0; ks < 2; ks++){
            int row = qh*32 + mt*16 + (grp & 1)*8 + ro;
            int col = h*32 + ks*16 + (grp >> 1)*8;
            ldm_x4(qah[mt][ks][0],qah[mt][ks][1],qah[mt][ks][2],qah[mt][ks][3],
                   smem_u32(&sQh[row*QSTR + col]));
            ldm_x4(qal[mt][ks][0],qal[mt][ks][1],qal[mt][ks][2],qal[mt][ks][3],
                   smem_u32(&sQl[row*QSTR + col]));
        }

    float o[2][4][4];
    #pragma unroll
    for (int mt = 0; mt < 2; mt++)
        #pragma unroll
        for (int nt = 0; nt < 4; nt++)
            #pragma unroll
            for (int i = 0; i < 4; i++) o[mt][nt][i] = 0.f;
    float mst[2][2] = {{-1e30f,-1e30f},{-1e30f,-1e30f}};
    float lst[2][2] = {{0.f,0.f},{0.f,0.f}};

    for (int tt = 0; tt < TOPK; tt++){
        int wsel = idx[bp*TOPK + tt];
        int bh2 = (wsel / NWIN)*WHS, bw2 = (wsel % NWIN)*WHS;
        __syncthreads();
        #pragma unroll
        for (int i = 0; i < 32; i++){
            int li = i*256 + tid;
            int k = li >> 7, c2 = (li & 127)*2;
            size_t tok = (size_t)(b*HH + bh2 + (k >> 3))*WWI + bw2 + (k & 7);
            float2 v = *(const float2*)(qkv + tok*QKVC + QKC + c2);
            if (c2 < 128){
                *(__nv_bfloat162*)&sKh[k*QSTR + c2] =
                    __nv_bfloat162(__float2bfloat16(v.x), __float2bfloat16(v.y));
            } else {
                int cv = c2 - 128;
                __nv_bfloat16 h0,l0,h1,l1;
                split_bf16(v.x,h0,l0); split_bf16(v.y,h1,l1);
                *(__nv_bfloat162*)&sVh[k*QSTR + cv] = __nv_bfloat162(h0,h1);
                *(__nv_bfloat162*)&sVl[k*QSTR + cv] = __nv_bfloat162(l0,l1);
            }
        }
        __syncthreads();

        float s[2][8][4];
        #pragma unroll
        for (int mt = 0; mt < 2; mt++)
            #pragma unroll
            for (int nt = 0; nt < 8; nt++)
                #pragma unroll
                for (int i = 0; i < 4; i++) s[mt][nt][i] = 0.f;
        #pragma unroll
        for (int ks = 0; ks < 2; ks++){
            uint32_t kb[8][2];
            int col = h*32 + ks*16 + (grp & 1)*8;
            #pragma unroll
            for (int j = 0; j < 4; j++){
                int row = j*16 + (grp >> 1)*8 + ro;
                uint32_t r0,r1,r2,r3;
                ldm_x4(r0,r1,r2,r3, smem_u32(&sKh[row*QSTR + col]));
                kb[2*j][0]=r0; kb[2*j][1]=r1; kb[2*j+1][0]=r2; kb[2*j+1][1]=r3;
            }
            #pragma unroll
            for (int mt = 0; mt < 2; mt++)
                #pragma unroll
                for (int nt = 0; nt < 8; nt++){
                    mma_bf16(s[mt][nt], qah[mt][ks], kb[nt]);
                    mma_bf16(s[mt][nt], qal[mt][ks], kb[nt]);
                }
        }

        uint32_t pa[2][4][4];
        #pragma unroll
        for (int mt = 0; mt < 2; mt++){
            float r0 = -1e30f, r1 = -1e30f;
            #pragma unroll
            for (int nt = 0; nt < 8; nt++){
                r0 = fmaxf(r0, fmaxf(s[mt][nt][0], s[mt][nt][1]));
                r1 = fmaxf(r1, fmaxf(s[mt][nt][2], s[mt][nt][3]));
            }
            r0 = fmaxf(r0, __shfl_xor_sync(0xffffffffu, r0, 1));
            r0 = fmaxf(r0, __shfl_xor_sync(0xffffffffu, r0, 2));
            r1 = fmaxf(r1, __shfl_xor_sync(0xffffffffu, r1, 1));
            r1 = fmaxf(r1, __shfl_xor_sync(0xffffffffu, r1, 2));
            float mn0 = fmaxf(mst[mt][0], r0), mn1 = fmaxf(mst[mt][1], r1);
            float c0 = __expf(mst[mt][0] - mn0), c1 = __expf(mst[mt][1] - mn1);
            mst[mt][0] = mn0; mst[mt][1] = mn1;
            float ls0 = 0.f, ls1 = 0.f;
            #pragma unroll
            for (int nt = 0; nt < 8; nt++){
                float e0 = __expf(s[mt][nt][0] - mn0);
                float e1 = __expf(s[mt][nt][1] - mn0);
                float e2 = __expf(s[mt][nt][2] - mn1);
                float e3 = __expf(s[mt][nt][3] - mn1);
                ls0 += e0 + e1; ls1 += e2 + e3;
                s[mt][nt][0] = e0; s[mt][nt][1] = e1;
                s[mt][nt][2] = e2; s[mt][nt][3] = e3;
            }
            ls0 += __shfl_xor_sync(0xffffffffu, ls0, 1);
            ls0 += __shfl_xor_sync(0xffffffffu, ls0, 2);
            ls1 += __shfl_xor_sync(0xffffffffu, ls1, 1);
            ls1 += __shfl_xor_sync(0xffffffffu, ls1, 2);
            lst[mt][0] = lst[mt][0]*c0 + ls0;
            lst[mt][1] = lst[mt][1]*c1 + ls1;
            #pragma unroll
            for (int nt = 0; nt < 4; nt++){
                o[mt][nt][0] *= c0; o[mt][nt][1] *= c0;
                o[mt][nt][2] *= c1; o[mt][nt][3] *= c1;
            }
            #pragma unroll
            for (int k2 = 0; k2 < 4; k2++){
                pa[mt][k2][0] = packbf2(s[mt][2*k2][0],   s[mt][2*k2][1]);
                pa[mt][k2][1] = packbf2(s[mt][2*k2][2],   s[mt][2*k2][3]);
                pa[mt][k2][2] = packbf2(s[mt][2*k2+1][0], s[mt][2*k2+1][1]);
                pa[mt][k2][3] = packbf2(s[mt][2*k2+1][2], s[mt][2*k2+1][3]);
            }
        }

        #pragma unroll
        for (int k2 = 0; k2 < 4; k2++){
            uint32_t vbh[4][2], vbl[4][2];
            int row = k2*16 + (grp & 1)*8 + ro;
            #pragma unroll
            for (int np = 0; np < 2; np++){
                int col = h*32 + np*16 + (grp >> 1)*8;
                uint32_t r0,r1,r2,r3;
                ldm_x4_t(r0,r1,r2,r3, smem_u32(&sVh[row*QSTR + col]));
                vbh[2*np][0]=r0; vbh[2*np][1]=r1; vbh[2*np+1][0]=r2; vbh[2*np+1][1]=r3;
                ldm_x4_t(r0,r1,r2,r3, smem_u32(&sVl[row*QSTR + col]));
                vbl[2*np][0]=r0; vbl[2*np][1]=r1; vbl[2*np+1][0]=r2; vbl[2*np+1][1]=r3;
            }
            #pragma unroll
            for (int mt = 0; mt < 2; mt++)
                #pragma unroll
                for (int nt = 0; nt < 4; nt++){
                    mma_bf16(o[mt][nt], pa[mt][k2], vbh[nt]);
                    mma_bf16(o[mt][nt], pa[mt][k2], vbl[nt]);
                }
        }
    }

    #pragma unroll
    for (int mt = 0; mt < 2; mt++){
        float inv0 = 1.f / lst[mt][0], inv1 = 1.f / lst[mt][1];
        int r0 = qh*32 + mt*16 + g, r1 = r0 + 8;
        size_t tok0 = (size_t)(b*HH + hb + (r0 >> 3))*WWI + wb + (r0 & 7);
        size_t tok1 = (size_t)(b*HH + hb + (r1 >> 3))*WWI + wb + (r1 & 7);
        #pragma unroll
        for (int nt = 0; nt < 4; nt++){
            int col = h*32 + nt*8 + t4*2;
            float2 v0; v0.x = o[mt][nt][0]*inv0; v0.y = o[mt][nt][1]*inv0;
            float2 v1; v1.x = o[mt][nt][2]*inv1; v1.y = o[mt][nt][3]*inv1;
            *(float2*)(op + tok0*CC + col) = v0;
            *(float2*)(op + tok1*CC + col) = v1;
        }
    }
}
#define ATTN_SMEM (5*QSZ*2)

// ---------------- kernel 7: LEPE 5x5 dwconv on v, add att, write bf16 (hi only) ----------------
__global__ __launch_bounds__(256) void k_lepe(const float* __restrict__ qkv,
                                              const float* __restrict__ lw,
                                              const float* __restrict__ lb,
                                              const float* __restrict__ att,
                                              __nv_bfloat16* __restrict__ oh){
    __shared__ __align__(16) float s[5*32*57];
    int bh = blockIdx.x; int b = bh / HH, h = bh % HH;
    int c0 = blockIdx.y * 32;
    int tid = threadIdx.x;
    for (int l = tid; l < 5*32*56; l += 256){
        int row = l / (32*56);
        int rem = l - row*(32*56);
        int wv  = rem >> 5;
        int c   = rem & 31;
        int hr  = h + row - 2;
        float v = 0.f;
        if (hr >= 0 && hr < HH)
            v = qkv[((size_t)((b*HH + hr)*WWI + wv))*QKVC + 2*QKC + c0 + c];
        s[row*32*57 + c*57 + wv] = v;
    }
    __syncthreads();
    int c = tid & 31;
    float wg[25];
    #pragma unroll
    for (int t = 0; t < 25; t++) wg[t] = lw[(c0 + c)*25 + t];
    float bias = lb[c0 + c];
    for (int l = tid; l < 56*32; l += 256){
        int w = l >> 5;
        float acc = bias;
        #pragma unroll
        for (int ky = 0; ky < 5; ky++){
            const float* srow = &s[ky*32*57 + c*57];
            #pragma unroll
            for (int kx = 0; kx < 5; kx++){
                int ww = w + kx - 2;
                if (ww >= 0 && ww < WWI) acc += wg[ky*5+kx] * srow[ww];
            }
        }
        size_t go = ((size_t)((b*HH + h)*WWI + w))*CC + c0 + c;
        oh[go] = __float2bfloat16(att[go] + acc);
    }
}

// ---------------- kernel 8: NHWC -> NCHW ----------------
__global__ void k_tr(const float* __restrict__ in, float* __restrict__ out){
    __shared__ float t[32][33];
    int b = blockIdx.z, c0 = blockIdx.y*32, p0 = blockIdx.x*32;
    int tx = threadIdx.x, ty = threadIdx.y;
    #pragma unroll
    for (int u = 0; u < 4; u++)
        t[ty + u*8][tx] = in[((size_t)(b*(HH*WWI) + p0 + ty + u*8))*CC + c0 + tx];
    __syncthreads();
    #pragma unroll
    for (int u = 0; u < 4; u++)
        out[((size_t)(b*CC + c0 + ty + u*8))*(HH*WWI) + p0 + tx] = t[tx][ty + u*8];
}

// ---------------- launcher ----------------
extern "C" void kernel_launch(void* const* d_in, const int* in_sizes, int n_in,
                              void* d_out, int out_size){
    const float* x      = (const float*)d_in[0];
    const float* pos_w  = (const float*)d_in[1];
    const float* pos_b  = (const float*)d_in[2];
    const float* ln1_g  = (const float*)d_in[3];
    const float* ln1_b  = (const float*)d_in[4];
    const float* qkv_w  = (const float*)d_in[5];
    const float* qkv_b  = (const float*)d_in[6];
    const float* lepe_w = (const float*)d_in[7];
    const float* lepe_b = (const float*)d_in[8];
    const float* wo_w   = (const float*)d_in[9];
    const float* wo_b   = (const float*)d_in[10];
    const float* ln2_g  = (const float*)d_in[11];
    const float* ln2_b  = (const float*)d_in[12];
    const float* mlp_w1 = (const float*)d_in[13];
    const float* mlp_b1 = (const float*)d_in[14];
    const float* mlp_w2 = (const float*)d_in[15];
    const float* mlp_b2 = (const float*)d_in[16];
    float* out = (float*)d_out;

    float *p_xh, *p_qkv, *p_att, *p_qwin, *p_kwin;
    int *p_idx;
    __nv_bfloat16 *p_yh, *p_yl, *p_ath, *p_h1h;
    __nv_bfloat16 *p_wqh, *p_wql, *p_woh, *p_w1h, *p_w2h;
    cudaGetSymbolAddress((void**)&p_xh,  g_xh);
    cudaGetSymbolAddress((void**)&p_qkv, g_qkv);
    cudaGetSymbolAddress((void**)&p_att, g_att);
    cudaGetSymbolAddress((void**)&p_qwin,g_qwin);
    cudaGetSymbolAddress((void**)&p_kwin,g_kwin);
    cudaGetSymbolAddress((void**)&p_idx, g_idx);
    cudaGetSymbolAddress((void**)&p_yh,  g_yh);
    cudaGetSymbolAddress((void**)&p_yl,  g_yl);
    cudaGetSymbolAddress((void**)&p_ath, g_ath);
    cudaGetSymbolAddress((void**)&p_h1h, g_h1h);
    cudaGetSymbolAddress((void**)&p_wqh, g_wqh);
    cudaGetSymbolAddress((void**)&p_wql, g_wql);
    cudaGetSymbolAddress((void**)&p_woh, g_woh);
    cudaGetSymbolAddress((void**)&p_w1h, g_w1h);
    cudaGetSymbolAddress((void**)&p_w2h, g_w2h);

    cudaFuncSetAttribute(k_mma_gemm<0,3>, cudaFuncAttributeMaxDynamicSharedMemorySize, GEMM_SMEM);
    cudaFuncSetAttribute(k_mma_gemm<1,1>, cudaFuncAttributeMaxDynamicSharedMemorySize, GEMM_SMEM);
    cudaFuncSetAttribute(k_mma_gemm<2,1>, cudaFuncAttributeMaxDynamicSharedMemorySize, GEMM_SMEM);
    cudaFuncSetAttribute(k_attn, cudaFuncAttributeMaxDynamicSharedMemorySize, ATTN_SMEM);

    // 1. pos dwconv + residual -> xh (NHWC)
    k_posconv<<<dim3(BB*HH, 2), 256>>>(x, pos_w, pos_b, p_xh);
    // 2. LN1 -> split bf16 y (hi+lo: QKV is 3-term)
    k_ln<<<TOK/8, 256>>>(p_xh, ln1_g, ln1_b, p_yh, p_yl);
    // 3. fused weight transpose + split
    k_wsplit_all<<<640, 256>>>(qkv_w, wo_w, mlp_w1, mlp_w2,
                               p_wqh, p_wql, p_woh, p_w1h, p_w2h);
    // 4. QKV gemm -> qkv fp32 (3-term: routing depends on it)   [profiled launch]
    k_mma_gemm<0,3><<<dim3(TOK/128, QKVC/64), 256, GEMM_SMEM>>>(
        p_yh, p_yl, p_wqh, p_wql, qkv_b, nullptr, p_qkv, nullptr, nullptr, QKVC, CC);
    // 5. window means
    k_winmean<<<BB*P2, 256>>>(p_qkv, p_qwin, p_kwin);
    // 6. routing top-4
    k_route<<<BB*P2, 64>>>(p_qwin, p_kwin, p_idx);
    // 7. HMMA attention -> att fp32 (NHWC)
    k_attn<<<BB*P2, 256, ATTN_SMEM>>>(p_qkv, p_idx, p_att);
    // 8. lepe: att + dwconv5x5(v) -> bf16 hi
    k_lepe<<<dim3(BB*HH, 4), 256>>>(p_qkv, lepe_w, lepe_b, p_att, p_ath);
    // 9. wo gemm with residual (1-term): xh = xh + (att+lepe) @ wo + b
    k_mma_gemm<2,1><<<dim3(TOK/128, CC/64), 256, GEMM_SMEM>>>(
        p_ath, nullptr, p_woh, nullptr, wo_b, p_xh, p_xh, nullptr, nullptr, CC, CC);
    // 10. LN2 -> bf16 y (hi only: MLP1 is 1-term)
    k_ln<<<TOK/8, 256>>>(p_xh, ln2_g, ln2_b, p_yh, nullptr);
    // 11. mlp1 + gelu (1-term) -> bf16 h1 (hi only)
    k_mma_gemm<1,1><<<dim3(TOK/128, 3*CC/64), 256, GEMM_SMEM>>>(
        p_yh, nullptr, p_w1h, nullptr, mlp_b1, nullptr, nullptr, p_h1h, nullptr, 3*CC, CC);
    // 12. mlp2 with residual (1-term): xh = xh + h1 @ w2 + b
    k_mma_gemm<2,1><<<dim3(TOK/128, CC/64), 256, GEMM_SMEM>>>(
        p_h1h, nullptr, p_w2h, nullptr, mlp_b2, p_xh, p_xh, nullptr, nullptr, CC, 3*CC);
    // 13. NHWC -> NCHW
    k_tr<<<dim3((HH*WWI)/32, CC/32, BB), dim3(32, 8)>>>(p_xh, out);
}

// round 13
// speedup vs baseline: 1.2082x; 1.0236x over previous
#include <cuda_runtime.h>
#include <cuda_bf16.h>
#include <cstdint>

#define BB 16
#define CC 128
#define HH 56
#define WWI 56
#define TOK (BB*HH*WWI)          // 50176
#define QKC 128
#define QKVC 384
#define NWIN 7
#define WHS 8
#define P2 49
#define W2 64
#define TOPK 4
#define HEADS 4
#define HD 32
#define SCALE 0.08838834764831845f

typedef unsigned long long ull;

// ---------------- scratch (device globals; no allocation) ----------------
__device__ float g_xh [TOK*CC];
__device__ float g_qkv[TOK*QKVC];
__device__ float g_att[TOK*CC];
__device__ float g_my  [BB*P2*CC];     // window means of y
__device__ float g_qwin[BB*P2*CC];
__device__ float g_kwin[BB*P2*CC];
__device__ int   g_idx [BB*P2*TOPK];
// split-bf16 activations
__device__ __nv_bfloat16 g_yh [TOK*CC],  g_yl [TOK*CC];
__device__ __nv_bfloat16 g_ath[TOK*CC];
__device__ __nv_bfloat16 g_h1h[TOK*3*CC];
// bf16 weights, transposed to [N,K] (hi only)
__device__ __nv_bfloat16 g_wqh[QKVC*CC];
__device__ __nv_bfloat16 g_woh[CC*CC];
__device__ __nv_bfloat16 g_w1h[3*CC*CC];
__device__ __nv_bfloat16 g_w2h[CC*3*CC];

// ---------------- helpers ----------------
__device__ __forceinline__ uint32_t smem_u32(const void* p){
    uint32_t a;
    asm("{ .reg .u64 t; cvta.to.shared.u64 t, %1; cvt.u32.u64 %0, t; }" : "=r"(a) : "l"(p));
    return a;
}
__device__ __forceinline__ void ldm_x4(uint32_t& r0,uint32_t& r1,uint32_t& r2,uint32_t& r3, uint32_t addr){
    asm volatile("ldmatrix.sync.aligned.m8n8.x4.shared.b16 {%0,%1,%2,%3}, [%4];"
        : "=r"(r0),"=r"(r1),"=r"(r2),"=r"(r3) : "r"(addr));
}
__device__ __forceinline__ void ldm_x4_t(uint32_t& r0,uint32_t& r1,uint32_t& r2,uint32_t& r3, uint32_t addr){
    asm volatile("ldmatrix.sync.aligned.m8n8.x4.trans.shared.b16 {%0,%1,%2,%3}, [%4];"
        : "=r"(r0),"=r"(r1),"=r"(r2),"=r"(r3) : "r"(addr));
}
__device__ __forceinline__ void mma_bf16(float* d, const uint32_t* a, const uint32_t* b){
    asm volatile("mma.sync.aligned.m16n8k16.row.col.f32.bf16.bf16.f32 "
        "{%0,%1,%2,%3}, {%4,%5,%6,%7}, {%8,%9}, {%0,%1,%2,%3};"
        : "+f"(d[0]),"+f"(d[1]),"+f"(d[2]),"+f"(d[3])
        : "r"(a[0]),"r"(a[1]),"r"(a[2]),"r"(a[3]), "r"(b[0]),"r"(b[1]));
}
__device__ __forceinline__ uint32_t packbf2(float lo, float hi){
    uint32_t r;
    asm("cvt.rn.bf16x2.f32 %0, %1, %2;" : "=r"(r) : "f"(hi), "f"(lo));
    return r;
}
__device__ __forceinline__ float gelu_exact(float v){
    return 0.5f * v * (1.0f + erff(v * 0.70710678118654752f));
}
__device__ __forceinline__ void split_bf16(float v, __nv_bfloat16& h, __nv_bfloat16& l){
    h = __float2bfloat16(v);
    l = __float2bfloat16(v - __bfloat162float(h));
}

// ---------------- fused weight transpose (hi only, one launch) ----------------
__global__ __launch_bounds__(256) void k_wsplit_all(
    const float* __restrict__ qkv_w, const float* __restrict__ wo_w,
    const float* __restrict__ mlp_w1, const float* __restrict__ mlp_w2,
    __nv_bfloat16* __restrict__ wqh,
    __nv_bfloat16* __restrict__ woh,
    __nv_bfloat16* __restrict__ w1h,
    __nv_bfloat16* __restrict__ w2h)
{
    int blk = blockIdx.x;
    const float* src; __nv_bfloat16 *dh; int K, N, base;
    if (blk < 192)      { src = qkv_w;  dh = wqh; K = CC;   N = QKVC; base = 0;   }
    else if (blk < 256) { src = wo_w;   dh = woh; K = CC;   N = CC;   base = 192; }
    else if (blk < 448) { src = mlp_w1; dh = w1h; K = CC;   N = 3*CC; base = 256; }
    else                { src = mlp_w2; dh = w2h; K = 3*CC; N = CC;   base = 448; }
    int i = (blk - base) * 256 + threadIdx.x;
    if (i >= N * K) return;
    int n = i / K, k = i - n * K;
    dh[i] = __float2bfloat16(src[(size_t)k * N + n]);
}

// ---------------- kernel 1: x + dwconv3x3(x) -> xh (NHWC) ----------------
__global__ __launch_bounds__(256) void k_posconv(const float* __restrict__ x,
                                                 const float* __restrict__ pw,
                                                 const float* __restrict__ pb,
                                                 float* __restrict__ xh){
    __shared__ __align__(16) float s[3*64*57];
    int bh = blockIdx.x; int b = bh / HH, h = bh % HH;
    int c0 = blockIdx.y * 64;
    int tid = threadIdx.x;
    for (int l = tid; l < 3*64*56; l += 256){
        int row = l / (64*56);
        int rem = l - row*(64*56);
        int c   = rem / 56;
        int wv  = rem - c*56;
        int hr  = h + row - 1;
        float v = 0.f;
        if (hr >= 0 && hr < HH)
            v = x[((size_t)((b*CC + c0 + c)*HH + hr))*WWI + wv];
        s[row*64*57 + c*57 + wv] = v;
    }
    __syncthreads();
    int c = tid & 63;
    float wgt[9];
    #pragma unroll
    for (int t = 0; t < 9; t++) wgt[t] = pw[(c0 + c)*9 + t];
    float bias = pb[c0 + c];
    for (int l = tid; l < 56*64; l += 256){
        int w = l >> 6;
        float acc = bias;
        #pragma unroll
        for (int ky = 0; ky < 3; ky++){
            const float* srow = &s[ky*64*57 + c*57];
            #pragma unroll
            for (int kx = 0; kx < 3; kx++){
                int ww = w + kx - 1;
                if (ww >= 0 && ww < WWI) acc += wgt[ky*3+kx] * srow[ww];
            }
        }
        acc += s[1*64*57 + c*57 + w];   // residual (center x)
        xh[((size_t)((b*HH + h)*WWI + w))*CC + c0 + c] = acc;
    }
}

// ---------------- kernel 2: LayerNorm over C -> bf16 (lo optional) ----------------
__global__ __launch_bounds__(256) void k_ln(const float* __restrict__ in,
                                            const float* __restrict__ g,
                                            const float* __restrict__ bt,
                                            __nv_bfloat16* __restrict__ oh,
                                            __nv_bfloat16* __restrict__ ol){
    int warp = threadIdx.x >> 5, lane = threadIdx.x & 31;
    int tok = blockIdx.x * 8 + warp;
    const float4* ip = (const float4*)(in + (size_t)tok * CC);
    float4 v = ip[lane];
    float s = v.x + v.y + v.z + v.w;
    float q = v.x*v.x + v.y*v.y + v.z*v.z + v.w*v.w;
    #pragma unroll
    for (int o = 16; o; o >>= 1){
        s += __shfl_xor_sync(0xffffffffu, s, o);
        q += __shfl_xor_sync(0xffffffffu, q, o);
    }
    float m   = s * (1.f/128.f);
    float var = q * (1.f/128.f) - m*m;
    float r   = rsqrtf(var + 1e-6f);
    float4 gg = ((const float4*)g)[lane];
    float4 bb = ((const float4*)bt)[lane];
    float o0 = (v.x - m)*r*gg.x + bb.x;
    float o1 = (v.y - m)*r*gg.y + bb.y;
    float o2 = (v.z - m)*r*gg.z + bb.z;
    float o3 = (v.w - m)*r*gg.w + bb.w;
    __nv_bfloat16 h0,h1,h2,h3,l0,l1,l2,l3;
    split_bf16(o0,h0,l0); split_bf16(o1,h1,l1); split_bf16(o2,h2,l2); split_bf16(o3,h3,l3);
    size_t off = (size_t)tok * CC + lane*4;
    *(__nv_bfloat162*)(oh + off)     = __nv_bfloat162(h0, h1);
    *(__nv_bfloat162*)(oh + off + 2) = __nv_bfloat162(h2, h3);
    if (ol){
        *(__nv_bfloat162*)(ol + off)     = __nv_bfloat162(l0, l1);
        *(__nv_bfloat162*)(ol + off + 2) = __nv_bfloat162(l2, l3);
    }
}

// ---------------- HMMA GEMM: C[M,N] = A[M,K] @ W (128x64 tile) ----------------
// TERMS: 3 = Ah*Bh + Al*Bh + Ah*Bl ; 2 = Ah*Bh + Al*Bh ; 1 = Ah*Bh
// EPI: 0 = bias -> fp32 C ; 1 = bias+GELU -> bf16 C1 ; 2 = bias+residual R -> fp32 C
#define ASTR 72   // smem row stride in bf16 (144B: conflict-free ldmatrix)
template<int EPI, int TERMS>
__global__ __launch_bounds__(256) void k_mma_gemm(
    const __nv_bfloat16* __restrict__ Ah, const __nv_bfloat16* __restrict__ Al,
    const __nv_bfloat16* __restrict__ Bh, const __nv_bfloat16* __restrict__ Bl,
    const float* __restrict__ bias, const float* __restrict__ R,
    float* __restrict__ C, __nv_bfloat16* __restrict__ C1, __nv_bfloat16* __restrict__ C2,
    int N, int K)
{
    extern __shared__ __align__(16) __nv_bfloat16 sm[];
    __nv_bfloat16* sAh = sm;                    // 128 x ASTR
    __nv_bfloat16* sAl = sm + 128*ASTR;         // 128 x ASTR (TERMS>=2)
    __nv_bfloat16* sBh = sm + 2*128*ASTR;       // 64 x ASTR
    __nv_bfloat16* sBl = sm + 2*128*ASTR + 64*ASTR;

    int tid = threadIdx.x;
    int warp = tid >> 5, lane = tid & 31;
    int wy = warp >> 1, wx = warp & 1;          // wy: M (0..3), wx: N (0..1)
    int bm = blockIdx.x * 128, bn = blockIdx.y * 64;

    float d[2][4][4];
    #pragma unroll
    for (int mt = 0; mt < 2; mt++)
        #pragma unroll
        for (int nt = 0; nt < 4; nt++)
            #pragma unroll
            for (int i = 0; i < 4; i++) d[mt][nt][i] = 0.f;

    int lr = tid >> 3;          // 0..31
    int lc = (tid & 7) * 8;     // 0..56

    for (int kc = 0; kc < K; kc += 64){
        if (kc) __syncthreads();
        #pragma unroll
        for (int p = 0; p < 4; p++){
            int row = p*32 + lr;
            *(uint4*)&sAh[row*ASTR + lc] = *(const uint4*)(Ah + (size_t)(bm+row)*K + kc + lc);
            if (TERMS >= 2)
                *(uint4*)&sAl[row*ASTR + lc] = *(const uint4*)(Al + (size_t)(bm+row)*K + kc + lc);
        }
        #pragma unroll
        for (int p = 0; p < 2; p++){
            int row = p*32 + lr;
            *(uint4*)&sBh[row*ASTR + lc] = *(const uint4*)(Bh + (size_t)(bn+row)*K + kc + lc);
            if (TERMS == 3)
                *(uint4*)&sBl[row*ASTR + lc] = *(const uint4*)(Bl + (size_t)(bn+row)*K + kc + lc);
        }
        __syncthreads();
        #pragma unroll
        for (int ks = 0; ks < 4; ks++){
            uint32_t ah[2][4], al[2][4], bh[4][2], bl[4][2];
            #pragma unroll
            for (int mt = 0; mt < 2; mt++){
                int r = wy*32 + mt*16 + (lane & 15);
                int c = ks*16 + (lane >> 4)*8;
                ldm_x4(ah[mt][0],ah[mt][1],ah[mt][2],ah[mt][3], smem_u32(&sAh[r*ASTR + c]));
                if (TERMS >= 2)
                    ldm_x4(al[mt][0],al[mt][1],al[mt][2],al[mt][3], smem_u32(&sAl[r*ASTR + c]));
            }
            #pragma unroll
            for (int nn = 0; nn < 2; nn++){
                int g8 = lane >> 3;
                int n = wx*32 + nn*16 + ((g8 >> 1) ? 8 : 0) + (lane & 7);
                int c = ks*16 + (g8 & 1)*8;
                uint32_t r0,r1,r2,r3;
                ldm_x4(r0,r1,r2,r3, smem_u32(&sBh[n*ASTR + c]));
                bh[nn*2+0][0]=r0; bh[nn*2+0][1]=r1; bh[nn*2+1][0]=r2; bh[nn*2+1][1]=r3;
                if (TERMS == 3){
                    ldm_x4(r0,r1,r2,r3, smem_u32(&sBl[n*ASTR + c]));
                    bl[nn*2+0][0]=r0; bl[nn*2+0][1]=r1; bl[nn*2+1][0]=r2; bl[nn*2+1][1]=r3;
                }
            }
            #pragma unroll
            for (int mt = 0; mt < 2; mt++)
                #pragma unroll
                for (int nt = 0; nt < 4; nt++){
                    mma_bf16(d[mt][nt], ah[mt], bh[nt]);       // Ah*Bh
                    if (TERMS >= 2)
                        mma_bf16(d[mt][nt], al[mt], bh[nt]);   // Al*Bh
                    if (TERMS == 3)
                        mma_bf16(d[mt][nt], ah[mt], bl[nt]);   // Ah*Bl
                }
        }
    }

    int g = lane >> 2, t = lane & 3;
    #pragma unroll
    for (int mt = 0; mt < 2; mt++){
        #pragma unroll
        for (int nt = 0; nt < 4; nt++){
            int c = bn + wx*32 + nt*8 + t*2;
            float b0 = bias[c], b1 = bias[c+1];
            #pragma unroll
            for (int hr = 0; hr < 2; hr++){
                int r = bm + wy*32 + mt*16 + g + hr*8;
                float v0 = d[mt][nt][hr*2+0] + b0;
                float v1 = d[mt][nt][hr*2+1] + b1;
                size_t go = (size_t)r * N + c;
                if (EPI == 0){
                    float2 o; o.x = v0; o.y = v1;
                    *(float2*)(C + go) = o;
                } else if (EPI == 1){
                    v0 = gelu_exact(v0); v1 = gelu_exact(v1);
                    *(__nv_bfloat162*)(C1 + go) =
                        __nv_bfloat162(__float2bfloat16(v0), __float2bfloat16(v1));
                } else {
                    float2 rr = *(const float2*)(R + go);
                    float2 o; o.x = v0 + rr.x; o.y = v1 + rr.y;
                    *(float2*)(C + go) = o;
                }
            }
        }
    }
}
#define GEMM_SMEM ((2*128*ASTR + 2*64*ASTR) * 2)

// ---------------- kernel 4a: window means of y (reconstructed fp32) ----------------
__global__ __launch_bounds__(128) void k_winmean_y(const __nv_bfloat16* __restrict__ yh,
                                                   const __nv_bfloat16* __restrict__ yl,
                                                   float* __restrict__ my){
    int bp = blockIdx.x; int b = bp / P2, p = bp - b*P2;
    int c = threadIdx.x;
    int hb = (p / NWIN) * WHS, wb = (p % NWIN) * WHS;
    float s = 0.f;
    #pragma unroll 8
    for (int r = 0; r < W2; r++){
        size_t tok = (size_t)(b*HH + hb + (r >> 3))*WWI + wb + (r & 7);
        s += __bfloat162float(yh[tok*CC + c]) + __bfloat162float(yl[tok*CC + c]);
    }
    my[(size_t)bp*CC + c] = s * (1.f/64.f);
}

// ---------------- kernel 4b: exact routing projections qwin/kwin ----------------
// qwin[bp,c] = mean_y[bp,:] @ qkv_w[:, c] + qkv_b[c]   (c in 0..255)
__global__ __launch_bounds__(256) void k_routegemm(const float* __restrict__ my,
                                                   const float* __restrict__ qkv_w,
                                                   const float* __restrict__ qkv_b,
                                                   float* __restrict__ qwin,
                                                   float* __restrict__ kwin){
    __shared__ float m[CC];
    int bp = blockIdx.x;
    int t = threadIdx.x;
    if (t < CC) m[t] = my[(size_t)bp*CC + t];
    __syncthreads();
    float acc = qkv_b[t];
    #pragma unroll 8
    for (int k = 0; k < CC; k++)
        acc += m[k] * qkv_w[(size_t)k*QKVC + t];
    if (t < QKC) qwin[(size_t)bp*CC + t] = acc;
    else         kwin[(size_t)bp*CC + (t - QKC)] = acc;
}

// ---------------- kernel 5: routing logits + top-4 ----------------
__global__ __launch_bounds__(64) void k_route(const float* __restrict__ qwin,
                                              const float* __restrict__ kwin,
                                              int* __restrict__ idx){
    __shared__ float qr[128];
    __shared__ float lg[49];
    int bp = blockIdx.x; int b = bp / P2;
    int t = threadIdx.x;
    qr[t]      = qwin[(size_t)bp*CC + t];
    qr[t + 64] = qwin[(size_t)bp*CC + 64 + t];
    __syncthreads();
    if (t < P2){
        const float* kr = kwin + (size_t)(b*P2 + t)*CC;
        float s = 0.f;
        #pragma unroll 8
        for (int c = 0; c < CC; c++) s += qr[c] * kr[c];
        lg[t] = s;
    }
    __syncthreads();
    if (t == 0){
        unsigned long long used = 0ull;
        for (int r = 0; r < TOPK; r++){
            float best = -1e30f; int bi = 0;
            for (int j = 0; j < P2; j++)
                if (!((used >> j) & 1ull) && lg[j] > best){ best = lg[j]; bi = j; }
            used |= 1ull << bi;
            idx[bp*TOPK + r] = bi;
        }
    }
}

// ---------------- kernel 6: HMMA flash attention (V hi only) ----------------
#define QSTR 136                 // bf16 row stride (272B), conflict-free ldmatrix
#define QSZ  (64*QSTR)
__global__ __launch_bounds__(256) void k_attn(const float* __restrict__ qkv,
                                              const int* __restrict__ idx,
                                              float* __restrict__ op){
    extern __shared__ __align__(16) __nv_bfloat16 sm[];
    __nv_bfloat16* sQh = sm;
    __nv_bfloat16* sQl = sm + QSZ;
    __nv_bfloat16* sKh = sm + 2*QSZ;
    __nv_bfloat16* sVh = sm + 3*QSZ;

    int bp = blockIdx.x; int b = bp / P2, p = bp - b*P2;
    int tid = threadIdx.x;
    int warp = tid >> 5, lane = tid & 31;
    int h = warp >> 1, qh = warp & 1;
    int g = lane >> 2, t4 = lane & 3;
    int ro = lane & 7, grp = lane >> 3;
    int hb = (p / NWIN)*WHS, wb = (p % NWIN)*WHS;

    #pragma unroll
    for (int i = 0; i < 16; i++){
        int li = i*256 + tid;
        int r = li >> 6, c2 = (li & 63)*2;
        size_t tok = (size_t)(b*HH + hb + (r >> 3))*WWI + wb + (r & 7);
        float2 v = *(const float2*)(qkv + tok*QKVC + c2);
        v.x *= SCALE; v.y *= SCALE;
        __nv_bfloat16 h0,l0,h1,l1;
        split_bf16(v.x,h0,l0); split_bf16(v.y,h1,l1);
        *(__nv_bfloat162*)&sQh[r*QSTR + c2] = __nv_bfloat162(h0,h1);
        *(__nv_bfloat162*)&sQl[r*QSTR + c2] = __nv_bfloat162(l0,l1);
    }
    __syncthreads();

    uint32_t qah[2][2][4], qal[2][2][4];
    #pragma unroll
    for (int mt = 0; mt < 2; mt++)
        #pragma unroll
        for (int ks = 0; ks < 2; ks++){
            int row = qh*32 + mt*16 + (grp & 1)*8 + ro;
            int col = h*32 + ks*16 + (grp >> 1)*8;
            ldm_x4(qah[mt][ks][0],qah[mt][ks][1],qah[mt][ks][2],qah[mt][ks][3],
                   smem_u32(&sQh[row*QSTR + col]));
            ldm_x4(qal[mt][ks][0],qal[mt][ks][1],qal[mt][ks][2],qal[mt][ks][3],
                   smem_u32(&sQl[row*QSTR + col]));
        }

    float o[2][4][4];
    #pragma unroll
    for (int mt = 0; mt < 2; mt++)
        #pragma unroll
        for (int nt = 0; nt < 4; nt++)
            #pragma unroll
            for (int i = 0; i < 4; i++) o[mt][nt][i] = 0.f;
    float mst[2][2] = {{-1e30f,-1e30f},{-1e30f,-1e30f}};
    float lst[2][2] = {{0.f,0.f},{0.f,0.f}};

    for (int tt = 0; tt < TOPK; tt++){
        int wsel = idx[bp*TOPK + tt];
        int bh2 = (wsel / NWIN)*WHS, bw2 = (wsel % NWIN)*WHS;
        __syncthreads();
        #pragma unroll
        for (int i = 0; i < 32; i++){
            int li = i*256 + tid;
            int k = li >> 7, c2 = (li & 127)*2;
            size_t tok = (size_t)(b*HH + bh2 + (k >> 3))*WWI + bw2 + (k & 7);
            float2 v = *(const float2*)(qkv + tok*QKVC + QKC + c2);
            __nv_bfloat162 pk = __nv_bfloat162(__float2bfloat16(v.x), __float2bfloat16(v.y));
            if (c2 < 128) *(__nv_bfloat162*)&sKh[k*QSTR + c2] = pk;
            else          *(__nv_bfloat162*)&sVh[k*QSTR + (c2-128)] = pk;
        }
        __syncthreads();

        float s[2][8][4];
        #pragma unroll
        for (int mt = 0; mt < 2; mt++)
            #pragma unroll
            for (int nt = 0; nt < 8; nt++)
                #pragma unroll
                for (int i = 0; i < 4; i++) s[mt][nt][i] = 0.f;
        #pragma unroll
        for (int ks = 0; ks < 2; ks++){
            uint32_t kb[8][2];
            int col = h*32 + ks*16 + (grp & 1)*8;
            #pragma unroll
            for (int j = 0; j < 4; j++){
                int row = j*16 + (grp >> 1)*8 + ro;
                uint32_t r0,r1,r2,r3;
                ldm_x4(r0,r1,r2,r3, smem_u32(&sKh[row*QSTR + col]));
                kb[2*j][0]=r0; kb[2*j][1]=r1; kb[2*j+1][0]=r2; kb[2*j+1][1]=r3;
            }
            #pragma unroll
            for (int mt = 0; mt < 2; mt++)
                #pragma unroll
                for (int nt = 0; nt < 8; nt++){
                    mma_bf16(s[mt][nt], qah[mt][ks], kb[nt]);
                    mma_bf16(s[mt][nt], qal[mt][ks], kb[nt]);
                }
        }

        uint32_t pa[2][4][4];
        #pragma unroll
        for (int mt = 0; mt < 2; mt++){
            float r0 = -1e30f, r1 = -1e30f;
            #pragma unroll
            for (int nt = 0; nt < 8; nt++){
                r0 = fmaxf(r0, fmaxf(s[mt][nt][0], s[mt][nt][1]));
                r1 = fmaxf(r1, fmaxf(s[mt][nt][2], s[mt][nt][3]));
            }
            r0 = fmaxf(r0, __shfl_xor_sync(0xffffffffu, r0, 1));
            r0 = fmaxf(r0, __shfl_xor_sync(0xffffffffu, r0, 2));
            r1 = fmaxf(r1, __shfl_xor_sync(0xffffffffu, r1, 1));
            r1 = fmaxf(r1, __shfl_xor_sync(0xffffffffu, r1, 2));
            float mn0 = fmaxf(mst[mt][0], r0), mn1 = fmaxf(mst[mt][1], r1);
            float c0 = __expf(mst[mt][0] - mn0), c1 = __expf(mst[mt][1] - mn1);
            mst[mt][0] = mn0; mst[mt][1] = mn1;
            float ls0 = 0.f, ls1 = 0.f;
            #pragma unroll
            for (int nt = 0; nt < 8; nt++){
                float e0 = __expf(s[mt][nt][0] - mn0);
                float e1 = __expf(s[mt][nt][1] - mn0);
                float e2 = __expf(s[mt][nt][2] - mn1);
                float e3 = __expf(s[mt][nt][3] - mn1);
                ls0 += e0 + e1; ls1 += e2 + e3;
                s[mt][nt][0] = e0; s[mt][nt][1] = e1;
                s[mt][nt][2] = e2; s[mt][nt][3] = e3;
            }
            ls0 += __shfl_xor_sync(0xffffffffu, ls0, 1);
            ls0 += __shfl_xor_sync(0xffffffffu, ls0, 2);
            ls1 += __shfl_xor_sync(0xffffffffu, ls1, 1);
            ls1 += __shfl_xor_sync(0xffffffffu, ls1, 2);
            lst[mt][0] = lst[mt][0]*c0 + ls0;
            lst[mt][1] = lst[mt][1]*c1 + ls1;
            #pragma unroll
            for (int nt = 0; nt < 4; nt++){
                o[mt][nt][0] *= c0; o[mt][nt][1] *= c0;
                o[mt][nt][2] *= c1; o[mt][nt][3] *= c1;
            }
            #pragma unroll
            for (int k2 = 0; k2 < 4; k2++){
                pa[mt][k2][0] = packbf2(s[mt][2*k2][0],   s[mt][2*k2][1]);
                pa[mt][k2][1] = packbf2(s[mt][2*k2][2],   s[mt][2*k2][3]);
                pa[mt][k2][2] = packbf2(s[mt][2*k2+1][0], s[mt][2*k2+1][1]);
                pa[mt][k2][3] = packbf2(s[mt][2*k2+1][2], s[mt][2*k2+1][3]);
            }
        }

        #pragma unroll
        for (int k2 = 0; k2 < 4; k2++){
            uint32_t vbh[4][2];
            int row = k2*16 + (grp & 1)*8 + ro;
            #pragma unroll
            for (int np = 0; np < 2; np++){
                int col = h*32 + np*16 + (grp >> 1)*8;
                uint32_t r0,r1,r2,r3;
                ldm_x4_t(r0,r1,r2,r3, smem_u32(&sVh[row*QSTR + col]));
                vbh[2*np][0]=r0; vbh[2*np][1]=r1; vbh[2*np+1][0]=r2; vbh[2*np+1][1]=r3;
            }
            #pragma unroll
            for (int mt = 0; mt < 2; mt++)
                #pragma unroll
                for (int nt = 0; nt < 4; nt++)
                    mma_bf16(o[mt][nt], pa[mt][k2], vbh[nt]);
        }
    }

    #pragma unroll
    for (int mt = 0; mt < 2; mt++){
        float inv0 = 1.f / lst[mt][0], inv1 = 1.f / lst[mt][1];
        int r0 = qh*32 + mt*16 + g, r1 = r0 + 8;
        size_t tok0 = (size_t)(b*HH + hb + (r0 >> 3))*WWI + wb + (r0 & 7);
        size_t tok1 = (size_t)(b*HH + hb + (r1 >> 3))*WWI + wb + (r1 & 7);
        #pragma unroll
        for (int nt = 0; nt < 4; nt++){
            int col = h*32 + nt*8 + t4*2;
            float2 v0; v0.x = o[mt][nt][0]*inv0; v0.y = o[mt][nt][1]*inv0;
            float2 v1; v1.x = o[mt][nt][2]*inv1; v1.y = o[mt][nt][3]*inv1;
            *(float2*)(op + tok0*CC + col) = v0;
            *(float2*)(op + tok1*CC + col) = v1;
        }
    }
}
#define ATTN_SMEM (4*QSZ*2)

// ---------------- kernel 7: LEPE 5x5 dwconv on v, add att, write bf16 (hi only) ----------------
__global__ __launch_bounds__(256) void k_lepe(const float* __restrict__ qkv,
                                              const float* __restrict__ lw,
                                              const float* __restrict__ lb,
                                              const float* __restrict__ att,
                                              __nv_bfloat16* __restrict__ oh){
    __shared__ __align__(16) float s[5*32*57];
    int bh = blockIdx.x; int b = bh / HH, h = bh % HH;
    int c0 = blockIdx.y * 32;
    int tid = threadIdx.x;
    for (int l = tid; l < 5*32*56; l += 256){
        int row = l / (32*56);
        int rem = l - row*(32*56);
        int wv  = rem >> 5;
        int c   = rem & 31;
        int hr  = h + row - 2;
        float v = 0.f;
        if (hr >= 0 && hr < HH)
            v = qkv[((size_t)((b*HH + hr)*WWI + wv))*QKVC + 2*QKC + c0 + c];
        s[row*32*57 + c*57 + wv] = v;
    }
    __syncthreads();
    int c = tid & 31;
    float wg[25];
    #pragma unroll
    for (int t = 0; t < 25; t++) wg[t] = lw[(c0 + c)*25 + t];
    float bias = lb[c0 + c];
    for (int l = tid; l < 56*32; l += 256){
        int w = l >> 5;
        float acc = bias;
        #pragma unroll
        for (int ky = 0; ky < 5; ky++){
            const float* srow = &s[ky*32*57 + c*57];
            #pragma unroll
            for (int kx = 0; kx < 5; kx++){
                int ww = w + kx - 2;
                if (ww >= 0 && ww < WWI) acc += wg[ky*5+kx] * srow[ww];
            }
        }
        size_t go = ((size_t)((b*HH + h)*WWI + w))*CC + c0 + c;
        oh[go] = __float2bfloat16(att[go] + acc);
    }
}

// ---------------- kernel 8: NHWC -> NCHW ----------------
__global__ void k_tr(const float* __restrict__ in, float* __restrict__ out){
    __shared__ float t[32][33];
    int b = blockIdx.z, c0 = blockIdx.y*32, p0 = blockIdx.x*32;
    int tx = threadIdx.x, ty = threadIdx.y;
    #pragma unroll
    for (int u = 0; u < 4; u++)
        t[ty + u*8][tx] = in[((size_t)(b*(HH*WWI) + p0 + ty + u*8))*CC + c0 + tx];
    __syncthreads();
    #pragma unroll
    for (int u = 0; u < 4; u++)
        out[((size_t)(b*CC + c0 + ty + u*8))*(HH*WWI) + p0 + tx] = t[tx][ty + u*8];
}

// ---------------- launcher ----------------
extern "C" void kernel_launch(void* const* d_in, const int* in_sizes, int n_in,
                              void* d_out, int out_size){
    const float* x      = (const float*)d_in[0];
    const float* pos_w  = (const float*)d_in[1];
    const float* pos_b  = (const float*)d_in[2];
    const float* ln1_g  = (const float*)d_in[3];
    const float* ln1_b  = (const float*)d_in[4];
    const float* qkv_w  = (const float*)d_in[5];
    const float* qkv_b  = (const float*)d_in[6];
    const float* lepe_w = (const float*)d_in[7];
    const float* lepe_b = (const float*)d_in[8];
    const float* wo_w   = (const float*)d_in[9];
    const float* wo_b   = (const float*)d_in[10];
    const float* ln2_g  = (const float*)d_in[11];
    const float* ln2_b  = (const float*)d_in[12];
    const float* mlp_w1 = (const float*)d_in[13];
    const float* mlp_b1 = (const float*)d_in[14];
    const float* mlp_w2 = (const float*)d_in[15];
    const float* mlp_b2 = (const float*)d_in[16];
    float* out = (float*)d_out;

    float *p_xh, *p_qkv, *p_att, *p_my, *p_qwin, *p_kwin;
    int *p_idx;
    __nv_bfloat16 *p_yh, *p_yl, *p_ath, *p_h1h;
    __nv_bfloat16 *p_wqh, *p_woh, *p_w1h, *p_w2h;
    cudaGetSymbolAddress((void**)&p_xh,  g_xh);
    cudaGetSymbolAddress((void**)&p_qkv, g_qkv);
    cudaGetSymbolAddress((void**)&p_att, g_att);
    cudaGetSymbolAddress((void**)&p_my,  g_my);
    cudaGetSymbolAddress((void**)&p_qwin,g_qwin);
    cudaGetSymbolAddress((void**)&p_kwin,g_kwin);
    cudaGetSymbolAddress((void**)&p_idx, g_idx);
    cudaGetSymbolAddress((void**)&p_yh,  g_yh);
    cudaGetSymbolAddress((void**)&p_yl,  g_yl);
    cudaGetSymbolAddress((void**)&p_ath, g_ath);
    cudaGetSymbolAddress((void**)&p_h1h, g_h1h);
    cudaGetSymbolAddress((void**)&p_wqh, g_wqh);
    cudaGetSymbolAddress((void**)&p_woh, g_woh);
    cudaGetSymbolAddress((void**)&p_w1h, g_w1h);
    cudaGetSymbolAddress((void**)&p_w2h, g_w2h);

    cudaFuncSetAttribute(k_mma_gemm<0,2>, cudaFuncAttributeMaxDynamicSharedMemorySize, GEMM_SMEM);
    cudaFuncSetAttribute(k_mma_gemm<1,1>, cudaFuncAttributeMaxDynamicSharedMemorySize, GEMM_SMEM);
    cudaFuncSetAttribute(k_mma_gemm<2,1>, cudaFuncAttributeMaxDynamicSharedMemorySize, GEMM_SMEM);
    cudaFuncSetAttribute(k_attn, cudaFuncAttributeMaxDynamicSharedMemorySize, ATTN_SMEM);

    // 1. pos dwconv + residual -> xh (NHWC)
    k_posconv<<<dim3(BB*HH, 2), 256>>>(x, pos_w, pos_b, p_xh);
    // 2. LN1 -> split bf16 y (hi+lo: QKV is 2-term)
    k_ln<<<TOK/8, 256>>>(p_xh, ln1_g, ln1_b, p_yh, p_yl);
    // 3. fused weight transpose (hi only)
    k_wsplit_all<<<640, 256>>>(qkv_w, wo_w, mlp_w1, mlp_w2,
                               p_wqh, p_woh, p_w1h, p_w2h);
    // 4. QKV gemm -> qkv fp32 (2-term)   [profiled launch]
    k_mma_gemm<0,2><<<dim3(TOK/128, QKVC/64), 256, GEMM_SMEM>>>(
        p_yh, p_yl, p_wqh, nullptr, qkv_b, nullptr, p_qkv, nullptr, nullptr, QKVC, CC);
    // 5a. window means of y (exact)
    k_winmean_y<<<BB*P2, 128>>>(p_yh, p_yl, p_my);
    // 5b. exact fp32 routing projections
    k_routegemm<<<BB*P2, 256>>>(p_my, qkv_w, qkv_b, p_qwin, p_kwin);
    // 6. routing top-4 (exact logits)
    k_route<<<BB*P2, 64>>>(p_qwin, p_kwin, p_idx);
    // 7. HMMA attention -> att fp32 (NHWC), V hi only
    k_attn<<<BB*P2, 256, ATTN_SMEM>>>(p_qkv, p_idx, p_att);
    // 8. lepe: att + dwconv5x5(v) -> bf16 hi
    k_lepe<<<dim3(BB*HH, 4), 256>>>(p_qkv, lepe_w, lepe_b, p_att, p_ath);
    // 9. wo gemm with residual (1-term): xh = xh + (att+lepe) @ wo + b
    k_mma_gemm<2,1><<<dim3(TOK/128, CC/64), 256, GEMM_SMEM>>>(
        p_ath, nullptr, p_woh, nullptr, wo_b, p_xh, p_xh, nullptr, nullptr, CC, CC);
    // 10. LN2 -> bf16 y (hi only)
    k_ln<<<TOK/8, 256>>>(p_xh, ln2_g, ln2_b, p_yh, nullptr);
    // 11. mlp1 + gelu (1-term) -> bf16 h1
    k_mma_gemm<1,1><<<dim3(TOK/128, 3*CC/64), 256, GEMM_SMEM>>>(
        p_yh, nullptr, p_w1h, nullptr, mlp_b1, nullptr, nullptr, p_h1h, nullptr, 3*CC, CC);
    // 12. mlp2 with residual (1-term): xh = xh + h1 @ w2 + b
    k_mma_gemm<2,1><<<dim3(TOK/128, CC/64), 256, GEMM_SMEM>>>(
        p_h1h, nullptr, p_w2h, nullptr, mlp_b2, p_xh, p_xh, nullptr, nullptr, CC, 3*CC);
    // 13. NHWC -> NCHW
    k_tr<<<dim3((HH*WWI)/32, CC/32, BB), dim3(32, 8)>>>(p_xh, out);
}

// round 14
// speedup vs baseline: 1.2699x; 1.0511x over previous
#include <cuda_runtime.h>
#include <cuda_bf16.h>
#include <cstdint>

#define BB 16
#define CC 128
#define HH 56
#define WWI 56
#define TOK (BB*HH*WWI)          // 50176
#define QKC 128
#define QKVC 384
#define NWIN 7
#define WHS 8
#define P2 49
#define W2 64
#define TOPK 4
#define HEADS 4
#define HD 32
#define SCALE 0.08838834764831845f

typedef unsigned long long ull;

// ---------------- scratch (device globals; no allocation) ----------------
__device__ float g_xh [TOK*CC];
__device__ float g_qkv[TOK*QKVC];
__device__ float g_att[TOK*CC];
__device__ float g_qwin[BB*P2*CC];
__device__ float g_kwin[BB*P2*CC];
__device__ int   g_idx [BB*P2*TOPK];
// split-bf16 activations
__device__ __nv_bfloat16 g_yh [TOK*CC],  g_yl [TOK*CC];
__device__ __nv_bfloat16 g_ath[TOK*CC];
__device__ __nv_bfloat16 g_h1h[TOK*3*CC];
// bf16 weights, transposed to [N,K] (hi only)
__device__ __nv_bfloat16 g_wqh[QKVC*CC];
__device__ __nv_bfloat16 g_woh[CC*CC];
__device__ __nv_bfloat16 g_w1h[3*CC*CC];
__device__ __nv_bfloat16 g_w2h[CC*3*CC];

// ---------------- helpers ----------------
__device__ __forceinline__ uint32_t smem_u32(const void* p){
    uint32_t a;
    asm("{ .reg .u64 t; cvta.to.shared.u64 t, %1; cvt.u32.u64 %0, t; }" : "=r"(a) : "l"(p));
    return a;
}
__device__ __forceinline__ void ldm_x4(uint32_t& r0,uint32_t& r1,uint32_t& r2,uint32_t& r3, uint32_t addr){
    asm volatile("ldmatrix.sync.aligned.m8n8.x4.shared.b16 {%0,%1,%2,%3}, [%4];"
        : "=r"(r0),"=r"(r1),"=r"(r2),"=r"(r3) : "r"(addr));
}
__device__ __forceinline__ void ldm_x4_t(uint32_t& r0,uint32_t& r1,uint32_t& r2,uint32_t& r3, uint32_t addr){
    asm volatile("ldmatrix.sync.aligned.m8n8.x4.trans.shared.b16 {%0,%1,%2,%3}, [%4];"
        : "=r"(r0),"=r"(r1),"=r"(r2),"=r"(r3) : "r"(addr));
}
__device__ __forceinline__ void mma_bf16(float* d, const uint32_t* a, const uint32_t* b){
    asm volatile("mma.sync.aligned.m16n8k16.row.col.f32.bf16.bf16.f32 "
        "{%0,%1,%2,%3}, {%4,%5,%6,%7}, {%8,%9}, {%0,%1,%2,%3};"
        : "+f"(d[0]),"+f"(d[1]),"+f"(d[2]),"+f"(d[3])
        : "r"(a[0]),"r"(a[1]),"r"(a[2]),"r"(a[3]), "r"(b[0]),"r"(b[1]));
}
__device__ __forceinline__ uint32_t packbf2(float lo, float hi){
    uint32_t r;
    asm("cvt.rn.bf16x2.f32 %0, %1, %2;" : "=r"(r) : "f"(hi), "f"(lo));
    return r;
}
__device__ __forceinline__ float gelu_exact(float v){
    return 0.5f * v * (1.0f + erff(v * 0.70710678118654752f));
}
__device__ __forceinline__ void split_bf16(float v, __nv_bfloat16& h, __nv_bfloat16& l){
    h = __float2bfloat16(v);
    l = __float2bfloat16(v - __bfloat162float(h));
}

// ---------------- fused weight transpose (hi only, one launch) ----------------
__global__ __launch_bounds__(256) void k_wsplit_all(
    const float* __restrict__ qkv_w, const float* __restrict__ wo_w,
    const float* __restrict__ mlp_w1, const float* __restrict__ mlp_w2,
    __nv_bfloat16* __restrict__ wqh,
    __nv_bfloat16* __restrict__ woh,
    __nv_bfloat16* __restrict__ w1h,
    __nv_bfloat16* __restrict__ w2h)
{
    int blk = blockIdx.x;
    const float* src; __nv_bfloat16 *dh; int K, N, base;
    if (blk < 192)      { src = qkv_w;  dh = wqh; K = CC;   N = QKVC; base = 0;   }
    else if (blk < 256) { src = wo_w;   dh = woh; K = CC;   N = CC;   base = 192; }
    else if (blk < 448) { src = mlp_w1; dh = w1h; K = CC;   N = 3*CC; base = 256; }
    else                { src = mlp_w2; dh = w2h; K = 3*CC; N = CC;   base = 448; }
    int i = (blk - base) * 256 + threadIdx.x;
    if (i >= N * K) return;
    int n = i / K, k = i - n * K;
    dh[i] = __float2bfloat16(src[(size_t)k * N + n]);
}

// ---------------- kernel 1: x + dwconv3x3(x) -> xh (NHWC) ----------------
__global__ __launch_bounds__(256) void k_posconv(const float* __restrict__ x,
                                                 const float* __restrict__ pw,
                                                 const float* __restrict__ pb,
                                                 float* __restrict__ xh){
    __shared__ __align__(16) float s[3*64*57];
    int bh = blockIdx.x; int b = bh / HH, h = bh % HH;
    int c0 = blockIdx.y * 64;
    int tid = threadIdx.x;
    for (int l = tid; l < 3*64*56; l += 256){
        int row = l / (64*56);
        int rem = l - row*(64*56);
        int c   = rem / 56;
        int wv  = rem - c*56;
        int hr  = h + row - 1;
        float v = 0.f;
        if (hr >= 0 && hr < HH)
            v = x[((size_t)((b*CC + c0 + c)*HH + hr))*WWI + wv];
        s[row*64*57 + c*57 + wv] = v;
    }
    __syncthreads();
    int c = tid & 63;
    float wgt[9];
    #pragma unroll
    for (int t = 0; t < 9; t++) wgt[t] = pw[(c0 + c)*9 + t];
    float bias = pb[c0 + c];
    for (int l = tid; l < 56*64; l += 256){
        int w = l >> 6;
        float acc = bias;
        #pragma unroll
        for (int ky = 0; ky < 3; ky++){
            const float* srow = &s[ky*64*57 + c*57];
            #pragma unroll
            for (int kx = 0; kx < 3; kx++){
                int ww = w + kx - 1;
                if (ww >= 0 && ww < WWI) acc += wgt[ky*3+kx] * srow[ww];
            }
        }
        acc += s[1*64*57 + c*57 + w];   // residual (center x)
        xh[((size_t)((b*HH + h)*WWI + w))*CC + c0 + c] = acc;
    }
}

// ---------------- kernel 2: LayerNorm over C -> bf16 (lo optional) ----------------
__global__ __launch_bounds__(256) void k_ln(const float* __restrict__ in,
                                            const float* __restrict__ g,
                                            const float* __restrict__ bt,
                                            __nv_bfloat16* __restrict__ oh,
                                            __nv_bfloat16* __restrict__ ol){
    int warp = threadIdx.x >> 5, lane = threadIdx.x & 31;
    int tok = blockIdx.x * 8 + warp;
    const float4* ip = (const float4*)(in + (size_t)tok * CC);
    float4 v = ip[lane];
    float s = v.x + v.y + v.z + v.w;
    float q = v.x*v.x + v.y*v.y + v.z*v.z + v.w*v.w;
    #pragma unroll
    for (int o = 16; o; o >>= 1){
        s += __shfl_xor_sync(0xffffffffu, s, o);
        q += __shfl_xor_sync(0xffffffffu, q, o);
    }
    float m   = s * (1.f/128.f);
    float var = q * (1.f/128.f) - m*m;
    float r   = rsqrtf(var + 1e-6f);
    float4 gg = ((const float4*)g)[lane];
    float4 bb = ((const float4*)bt)[lane];
    float o0 = (v.x - m)*r*gg.x + bb.x;
    float o1 = (v.y - m)*r*gg.y + bb.y;
    float o2 = (v.z - m)*r*gg.z + bb.z;
    float o3 = (v.w - m)*r*gg.w + bb.w;
    __nv_bfloat16 h0,h1,h2,h3,l0,l1,l2,l3;
    split_bf16(o0,h0,l0); split_bf16(o1,h1,l1); split_bf16(o2,h2,l2); split_bf16(o3,h3,l3);
    size_t off = (size_t)tok * CC + lane*4;
    *(__nv_bfloat162*)(oh + off)     = __nv_bfloat162(h0, h1);
    *(__nv_bfloat162*)(oh + off + 2) = __nv_bfloat162(h2, h3);
    if (ol){
        *(__nv_bfloat162*)(ol + off)     = __nv_bfloat162(l0, l1);
        *(__nv_bfloat162*)(ol + off + 2) = __nv_bfloat162(l2, l3);
    }
}

// ---------------- HMMA GEMM: C[M,N] = A[M,K] @ W (128 x BN tile) ----------------
// TERMS: 2 = Ah*Bh + Al*Bh ; 1 = Ah*Bh
// EPI: 0 = bias -> fp32 C ; 1 = bias+GELU -> bf16 C1 ; 2 = bias+residual R -> fp32 C
#define ASTR 72   // smem row stride in bf16 (144B: conflict-free ldmatrix)
template<int EPI, int TERMS, int BN>
__global__ __launch_bounds__(256) void k_mma_gemm(
    const __nv_bfloat16* __restrict__ Ah, const __nv_bfloat16* __restrict__ Al,
    const __nv_bfloat16* __restrict__ Bh,
    const float* __restrict__ bias, const float* __restrict__ R,
    float* __restrict__ C, __nv_bfloat16* __restrict__ C1,
    int N, int K)
{
    extern __shared__ __align__(16) __nv_bfloat16 sm[];
    constexpr int NWX   = BN / 32;      // warps along N
    constexpr int NWY   = 8 / NWX;      // warps along M
    constexpr int MROWS = 128 / NWY;    // M rows per warp
    constexpr int MT    = MROWS / 16;   // m16 tiles per warp
    __nv_bfloat16* sAh = sm;
    __nv_bfloat16* sAl = sm + 128*ASTR;                             // TERMS==2
    __nv_bfloat16* sBh = sm + (TERMS >= 2 ? 2 : 1)*128*ASTR;

    int tid = threadIdx.x;
    int warp = tid >> 5, lane = tid & 31;
    int wy = warp / NWX, wx = warp % NWX;
    int bm = blockIdx.x * 128, bn = blockIdx.y * BN;

    float d[MT][4][4];
    #pragma unroll
    for (int mt = 0; mt < MT; mt++)
        #pragma unroll
        for (int nt = 0; nt < 4; nt++)
            #pragma unroll
            for (int i = 0; i < 4; i++) d[mt][nt][i] = 0.f;

    int lr = tid >> 3;          // 0..31
    int lc = (tid & 7) * 8;     // 0..56

    for (int kc = 0; kc < K; kc += 64){
        if (kc) __syncthreads();
        #pragma unroll
        for (int p = 0; p < 4; p++){
            int row = p*32 + lr;
            *(uint4*)&sAh[row*ASTR + lc] = *(const uint4*)(Ah + (size_t)(bm+row)*K + kc + lc);
            if (TERMS >= 2)
                *(uint4*)&sAl[row*ASTR + lc] = *(const uint4*)(Al + (size_t)(bm+row)*K + kc + lc);
        }
        #pragma unroll
        for (int p = 0; p < BN/32; p++){
            int row = p*32 + lr;
            *(uint4*)&sBh[row*ASTR + lc] = *(const uint4*)(Bh + (size_t)(bn+row)*K + kc + lc);
        }
        __syncthreads();
        #pragma unroll
        for (int ks = 0; ks < 4; ks++){
            uint32_t ah[MT][4], al[MT][4], bh[4][2];
            #pragma unroll
            for (int mt = 0; mt < MT; mt++){
                int r = wy*MROWS + mt*16 + (lane & 15);
                int c = ks*16 + (lane >> 4)*8;
                ldm_x4(ah[mt][0],ah[mt][1],ah[mt][2],ah[mt][3], smem_u32(&sAh[r*ASTR + c]));
                if (TERMS >= 2)
                    ldm_x4(al[mt][0],al[mt][1],al[mt][2],al[mt][3], smem_u32(&sAl[r*ASTR + c]));
            }
            #pragma unroll
            for (int nn = 0; nn < 2; nn++){
                int g8 = lane >> 3;
                int n = wx*32 + nn*16 + ((g8 >> 1) ? 8 : 0) + (lane & 7);
                int c = ks*16 + (g8 & 1)*8;
                uint32_t r0,r1,r2,r3;
                ldm_x4(r0,r1,r2,r3, smem_u32(&sBh[n*ASTR + c]));
                bh[nn*2+0][0]=r0; bh[nn*2+0][1]=r1; bh[nn*2+1][0]=r2; bh[nn*2+1][1]=r3;
            }
            #pragma unroll
            for (int mt = 0; mt < MT; mt++)
                #pragma unroll
                for (int nt = 0; nt < 4; nt++){
                    mma_bf16(d[mt][nt], ah[mt], bh[nt]);       // Ah*Bh
                    if (TERMS >= 2)
                        mma_bf16(d[mt][nt], al[mt], bh[nt]);   // Al*Bh
                }
        }
    }

    int g = lane >> 2, t = lane & 3;
    #pragma unroll
    for (int mt = 0; mt < MT; mt++){
        #pragma unroll
        for (int nt = 0; nt < 4; nt++){
            int c = bn + wx*32 + nt*8 + t*2;
            float b0 = bias[c], b1 = bias[c+1];
            #pragma unroll
            for (int hr = 0; hr < 2; hr++){
                int r = bm + wy*MROWS + mt*16 + g + hr*8;
                float v0 = d[mt][nt][hr*2+0] + b0;
                float v1 = d[mt][nt][hr*2+1] + b1;
                size_t go = (size_t)r * N + c;
                if (EPI == 0){
                    float2 o; o.x = v0; o.y = v1;
                    *(float2*)(C + go) = o;
                } else if (EPI == 1){
                    v0 = gelu_exact(v0); v1 = gelu_exact(v1);
                    *(__nv_bfloat162*)(C1 + go) =
                        __nv_bfloat162(__float2bfloat16(v0), __float2bfloat16(v1));
                } else {
                    float2 rr = *(const float2*)(R + go);
                    float2 o; o.x = v0 + rr.x; o.y = v1 + rr.y;
                    *(float2*)(C + go) = o;
                }
            }
        }
    }
}
#define GEMM_SMEM_T2 (3*128*ASTR*2)
#define GEMM_SMEM_T1 (2*128*ASTR*2)

// ---------------- kernel 4: fused window mean(y) + exact routing projections ----------------
// qwin[bp,c] = mean_y[bp,:] @ qkv_w[:, c] + qkv_b[c]  (c<128); kwin for c in 128..255
__global__ __launch_bounds__(256) void k_winroute(const __nv_bfloat16* __restrict__ yh,
                                                  const __nv_bfloat16* __restrict__ yl,
                                                  const float* __restrict__ qkv_w,
                                                  const float* __restrict__ qkv_b,
                                                  float* __restrict__ qwin,
                                                  float* __restrict__ kwin){
    __shared__ float part[256];
    __shared__ float m[CC];
    int bp = blockIdx.x; int b = bp / P2, p = bp - b*P2;
    int tid = threadIdx.x;
    int c = tid & 127, half = tid >> 7;
    int hb = (p / NWIN) * WHS, wb = (p % NWIN) * WHS;
    float s = 0.f;
    #pragma unroll 8
    for (int r = half*32; r < half*32 + 32; r++){
        size_t tok = (size_t)(b*HH + hb + (r >> 3))*WWI + wb + (r & 7);
        s += __bfloat162float(yh[tok*CC + c]) + __bfloat162float(yl[tok*CC + c]);
    }
    part[tid] = s;
    __syncthreads();
    if (tid < CC) m[tid] = (part[tid] + part[tid + 128]) * (1.f/64.f);
    __syncthreads();
    float acc = qkv_b[tid];
    #pragma unroll 8
    for (int k = 0; k < CC; k++)
        acc += m[k] * qkv_w[(size_t)k*QKVC + tid];
    if (tid < QKC) qwin[(size_t)bp*CC + tid] = acc;
    else           kwin[(size_t)bp*CC + (tid - QKC)] = acc;
}

// ---------------- kernel 5: routing logits + top-4 ----------------
__global__ __launch_bounds__(64) void k_route(const float* __restrict__ qwin,
                                              const float* __restrict__ kwin,
                                              int* __restrict__ idx){
    __shared__ float qr[128];
    __shared__ float lg[49];
    int bp = blockIdx.x; int b = bp / P2;
    int t = threadIdx.x;
    qr[t]      = qwin[(size_t)bp*CC + t];
    qr[t + 64] = qwin[(size_t)bp*CC + 64 + t];
    __syncthreads();
    if (t < P2){
        const float* kr = kwin + (size_t)(b*P2 + t)*CC;
        float s = 0.f;
        #pragma unroll 8
        for (int c = 0; c < CC; c++) s += qr[c] * kr[c];
        lg[t] = s;
    }
    __syncthreads();
    if (t == 0){
        unsigned long long used = 0ull;
        for (int r = 0; r < TOPK; r++){
            float best = -1e30f; int bi = 0;
            for (int j = 0; j < P2; j++)
                if (!((used >> j) & 1ull) && lg[j] > best){ best = lg[j]; bi = j; }
            used |= 1ull << bi;
            idx[bp*TOPK + r] = bi;
        }
    }
}

// ---------------- kernel 6: HMMA flash attention (Q hi, K hi, V hi) ----------------
#define QSTR 136                 // bf16 row stride (272B), conflict-free ldmatrix
#define QSZ  (64*QSTR)
__global__ __launch_bounds__(256) void k_attn(const float* __restrict__ qkv,
                                              const int* __restrict__ idx,
                                              float* __restrict__ op){
    extern __shared__ __align__(16) __nv_bfloat16 sm[];
    __nv_bfloat16* sQh = sm;
    __nv_bfloat16* sKh = sm + QSZ;
    __nv_bfloat16* sVh = sm + 2*QSZ;

    int bp = blockIdx.x; int b = bp / P2, p = bp - b*P2;
    int tid = threadIdx.x;
    int warp = tid >> 5, lane = tid & 31;
    int h = warp >> 1, qh = warp & 1;
    int g = lane >> 2, t4 = lane & 3;
    int ro = lane & 7, grp = lane >> 3;
    int hb = (p / NWIN)*WHS, wb = (p % NWIN)*WHS;

    #pragma unroll
    for (int i = 0; i < 16; i++){
        int li = i*256 + tid;
        int r = li >> 6, c2 = (li & 63)*2;
        size_t tok = (size_t)(b*HH + hb + (r >> 3))*WWI + wb + (r & 7);
        float2 v = *(const float2*)(qkv + tok*QKVC + c2);
        *(__nv_bfloat162*)&sQh[r*QSTR + c2] =
            __nv_bfloat162(__float2bfloat16(v.x * SCALE), __float2bfloat16(v.y * SCALE));
    }
    __syncthreads();

    uint32_t qah[2][2][4];
    #pragma unroll
    for (int mt = 0; mt < 2; mt++)
        #pragma unroll
        for (int ks = 0; ks < 2; ks++){
            int row = qh*32 + mt*16 + (grp & 1)*8 + ro;
            int col = h*32 + ks*16 + (grp >> 1)*8;
            ldm_x4(qah[mt][ks][0],qah[mt][ks][1],qah[mt][ks][2],qah[mt][ks][3],
                   smem_u32(&sQh[row*QSTR + col]));
        }

    float o[2][4][4];
    #pragma unroll
    for (int mt = 0; mt < 2; mt++)
        #pragma unroll
        for (int nt = 0; nt < 4; nt++)
            #pragma unroll
            for (int i = 0; i < 4; i++) o[mt][nt][i] = 0.f;
    float mst[2][2] = {{-1e30f,-1e30f},{-1e30f,-1e30f}};
    float lst[2][2] = {{0.f,0.f},{0.f,0.f}};

    for (int tt = 0; tt < TOPK; tt++){
        int wsel = idx[bp*TOPK + tt];
        int bh2 = (wsel / NWIN)*WHS, bw2 = (wsel % NWIN)*WHS;
        __syncthreads();
        #pragma unroll
        for (int i = 0; i < 32; i++){
            int li = i*256 + tid;
            int k = li >> 7, c2 = (li & 127)*2;
            size_t tok = (size_t)(b*HH + bh2 + (k >> 3))*WWI + bw2 + (k & 7);
            float2 v = *(const float2*)(qkv + tok*QKVC + QKC + c2);
            __nv_bfloat162 pk = __nv_bfloat162(__float2bfloat16(v.x), __float2bfloat16(v.y));
            if (c2 < 128) *(__nv_bfloat162*)&sKh[k*QSTR + c2] = pk;
            else          *(__nv_bfloat162*)&sVh[k*QSTR + (c2-128)] = pk;
        }
        __syncthreads();

        float s[2][8][4];
        #pragma unroll
        for (int mt = 0; mt < 2; mt++)
            #pragma unroll
            for (int nt = 0; nt < 8; nt++)
                #pragma unroll
                for (int i = 0; i < 4; i++) s[mt][nt][i] = 0.f;
        #pragma unroll
        for (int ks = 0; ks < 2; ks++){
            uint32_t kb[8][2];
            int col = h*32 + ks*16 + (grp & 1)*8;
            #pragma unroll
            for (int j = 0; j < 4; j++){
                int row = j*16 + (grp >> 1)*8 + ro;
                uint32_t r0,r1,r2,r3;
                ldm_x4(r0,r1,r2,r3, smem_u32(&sKh[row*QSTR + col]));
                kb[2*j][0]=r0; kb[2*j][1]=r1; kb[2*j+1][0]=r2; kb[2*j+1][1]=r3;
            }
            #pragma unroll
            for (int mt = 0; mt < 2; mt++)
                #pragma unroll
                for (int nt = 0; nt < 8; nt++)
                    mma_bf16(s[mt][nt], qah[mt][ks], kb[nt]);
        }

        uint32_t pa[2][4][4];
        #pragma unroll
        for (int mt = 0; mt < 2; mt++){
            float r0 = -1e30f, r1 = -1e30f;
            #pragma unroll
            for (int nt = 0; nt < 8; nt++){
                r0 = fmaxf(r0, fmaxf(s[mt][nt][0], s[mt][nt][1]));
                r1 = fmaxf(r1, fmaxf(s[mt][nt][2], s[mt][nt][3]));
            }
            r0 = fmaxf(r0, __shfl_xor_sync(0xffffffffu, r0, 1));
            r0 = fmaxf(r0, __shfl_xor_sync(0xffffffffu, r0, 2));
            r1 = fmaxf(r1, __shfl_xor_sync(0xffffffffu, r1, 1));
            r1 = fmaxf(r1, __shfl_xor_sync(0xffffffffu, r1, 2));
            float mn0 = fmaxf(mst[mt][0], r0), mn1 = fmaxf(mst[mt][1], r1);
            float c0 = __expf(mst[mt][0] - mn0), c1 = __expf(mst[mt][1] - mn1);
            mst[mt][0] = mn0; mst[mt][1] = mn1;
            float ls0 = 0.f, ls1 = 0.f;
            #pragma unroll
            for (int nt = 0; nt < 8; nt++){
                float e0 = __expf(s[mt][nt][0] - mn0);
                float e1 = __expf(s[mt][nt][1] - mn0);
                float e2 = __expf(s[mt][nt][2] - mn1);
                float e3 = __expf(s[mt][nt][3] - mn1);
                ls0 += e0 + e1; ls1 += e2 + e3;
                s[mt][nt][0] = e0; s[mt][nt][1] = e1;
                s[mt][nt][2] = e2; s[mt][nt][3] = e3;
            }
            ls0 += __shfl_xor_sync(0xffffffffu, ls0, 1);
            ls0 += __shfl_xor_sync(0xffffffffu, ls0, 2);
            ls1 += __shfl_xor_sync(0xffffffffu, ls1, 1);
            ls1 += __shfl_xor_sync(0xffffffffu, ls1, 2);
            lst[mt][0] = lst[mt][0]*c0 + ls0;
            lst[mt][1] = lst[mt][1]*c1 + ls1;
            #pragma unroll
            for (int nt = 0; nt < 4; nt++){
                o[mt][nt][0] *= c0; o[mt][nt][1] *= c0;
                o[mt][nt][2] *= c1; o[mt][nt][3] *= c1;
            }
            #pragma unroll
            for (int k2 = 0; k2 < 4; k2++){
                pa[mt][k2][0] = packbf2(s[mt][2*k2][0],   s[mt][2*k2][1]);
                pa[mt][k2][1] = packbf2(s[mt][2*k2][2],   s[mt][2*k2][3]);
                pa[mt][k2][2] = packbf2(s[mt][2*k2+1][0], s[mt][2*k2+1][1]);
                pa[mt][k2][3] = packbf2(s[mt][2*k2+1][2], s[mt][2*k2+1][3]);
            }
        }

        #pragma unroll
        for (int k2 = 0; k2 < 4; k2++){
            uint32_t vbh[4][2];
            int row = k2*16 + (grp & 1)*8 + ro;
            #pragma unroll
            for (int np = 0; np < 2; np++){
                int col = h*32 + np*16 + (grp >> 1)*8;
                uint32_t r0,r1,r2,r3;
                ldm_x4_t(r0,r1,r2,r3, smem_u32(&sVh[row*QSTR + col]));
                vbh[2*np][0]=r0; vbh[2*np][1]=r1; vbh[2*np+1][0]=r2; vbh[2*np+1][1]=r3;
            }
            #pragma unroll
            for (int mt = 0; mt < 2; mt++)
                #pragma unroll
                for (int nt = 0; nt < 4; nt++)
                    mma_bf16(o[mt][nt], pa[mt][k2], vbh[nt]);
        }
    }

    #pragma unroll
    for (int mt = 0; mt < 2; mt++){
        float inv0 = 1.f / lst[mt][0], inv1 = 1.f / lst[mt][1];
        int r0 = qh*32 + mt*16 + g, r1 = r0 + 8;
        size_t tok0 = (size_t)(b*HH + hb + (r0 >> 3))*WWI + wb + (r0 & 7);
        size_t tok1 = (size_t)(b*HH + hb + (r1 >> 3))*WWI + wb + (r1 & 7);
        #pragma unroll
        for (int nt = 0; nt < 4; nt++){
            int col = h*32 + nt*8 + t4*2;
            float2 v0; v0.x = o[mt][nt][0]*inv0; v0.y = o[mt][nt][1]*inv0;
            float2 v1; v1.x = o[mt][nt][2]*inv1; v1.y = o[mt][nt][3]*inv1;
            *(float2*)(op + tok0*CC + col) = v0;
            *(float2*)(op + tok1*CC + col) = v1;
        }
    }
}
#define ATTN_SMEM (3*QSZ*2)

// ---------------- kernel 7: LEPE 5x5 dwconv on v, add att, write bf16 (hi only) ----------------
__global__ __launch_bounds__(256) void k_lepe(const float* __restrict__ qkv,
                                              const float* __restrict__ lw,
                                              const float* __restrict__ lb,
                                              const float* __restrict__ att,
                                              __nv_bfloat16* __restrict__ oh){
    __shared__ __align__(16) float s[5*32*57];
    int bh = blockIdx.x; int b = bh / HH, h = bh % HH;
    int c0 = blockIdx.y * 32;
    int tid = threadIdx.x;
    for (int l = tid; l < 5*32*56; l += 256){
        int row = l / (32*56);
        int rem = l - row*(32*56);
        int wv  = rem >> 5;
        int c   = rem & 31;
        int hr  = h + row - 2;
        float v = 0.f;
        if (hr >= 0 && hr < HH)
            v = qkv[((size_t)((b*HH + hr)*WWI + wv))*QKVC + 2*QKC + c0 + c];
        s[row*32*57 + c*57 + wv] = v;
    }
    __syncthreads();
    int c = tid & 31;
    float wg[25];
    #pragma unroll
    for (int t = 0; t < 25; t++) wg[t] = lw[(c0 + c)*25 + t];
    float bias = lb[c0 + c];
    for (int l = tid; l < 56*32; l += 256){
        int w = l >> 5;
        float acc = bias;
        #pragma unroll
        for (int ky = 0; ky < 5; ky++){
            const float* srow = &s[ky*32*57 + c*57];
            #pragma unroll
            for (int kx = 0; kx < 5; kx++){
                int ww = w + kx - 2;
                if (ww >= 0 && ww < WWI) acc += wg[ky*5+kx] * srow[ww];
            }
        }
        size_t go = ((size_t)((b*HH + h)*WWI + w))*CC + c0 + c;
        oh[go] = __float2bfloat16(att[go] + acc);
    }
}

// ---------------- kernel 8: NHWC -> NCHW ----------------
__global__ void k_tr(const float* __restrict__ in, float* __restrict__ out){
    __shared__ float t[32][33];
    int b = blockIdx.z, c0 = blockIdx.y*32, p0 = blockIdx.x*32;
    int tx = threadIdx.x, ty = threadIdx.y;
    #pragma unroll
    for (int u = 0; u < 4; u++)
        t[ty + u*8][tx] = in[((size_t)(b*(HH*WWI) + p0 + ty + u*8))*CC + c0 + tx];
    __syncthreads();
    #pragma unroll
    for (int u = 0; u < 4; u++)
        out[((size_t)(b*CC + c0 + ty + u*8))*(HH*WWI) + p0 + tx] = t[tx][ty + u*8];
}

// ---------------- launcher ----------------
extern "C" void kernel_launch(void* const* d_in, const int* in_sizes, int n_in,
                              void* d_out, int out_size){
    const float* x      = (const float*)d_in[0];
    const float* pos_w  = (const float*)d_in[1];
    const float* pos_b  = (const float*)d_in[2];
    const float* ln1_g  = (const float*)d_in[3];
    const float* ln1_b  = (const float*)d_in[4];
    const float* qkv_w  = (const float*)d_in[5];
    const float* qkv_b  = (const float*)d_in[6];
    const float* lepe_w = (const float*)d_in[7];
    const float* lepe_b = (const float*)d_in[8];
    const float* wo_w   = (const float*)d_in[9];
    const float* wo_b   = (const float*)d_in[10];
    const float* ln2_g  = (const float*)d_in[11];
    const float* ln2_b  = (const float*)d_in[12];
    const float* mlp_w1 = (const float*)d_in[13];
    const float* mlp_b1 = (const float*)d_in[14];
    const float* mlp_w2 = (const float*)d_in[15];
    const float* mlp_b2 = (const float*)d_in[16];
    float* out = (float*)d_out;

    float *p_xh, *p_qkv, *p_att, *p_qwin, *p_kwin;
    int *p_idx;
    __nv_bfloat16 *p_yh, *p_yl, *p_ath, *p_h1h;
    __nv_bfloat16 *p_wqh, *p_woh, *p_w1h, *p_w2h;
    cudaGetSymbolAddress((void**)&p_xh,  g_xh);
    cudaGetSymbolAddress((void**)&p_qkv, g_qkv);
    cudaGetSymbolAddress((void**)&p_att, g_att);
    cudaGetSymbolAddress((void**)&p_qwin,g_qwin);
    cudaGetSymbolAddress((void**)&p_kwin,g_kwin);
    cudaGetSymbolAddress((void**)&p_idx, g_idx);
    cudaGetSymbolAddress((void**)&p_yh,  g_yh);
    cudaGetSymbolAddress((void**)&p_yl,  g_yl);
    cudaGetSymbolAddress((void**)&p_ath, g_ath);
    cudaGetSymbolAddress((void**)&p_h1h, g_h1h);
    cudaGetSymbolAddress((void**)&p_wqh, g_wqh);
    cudaGetSymbolAddress((void**)&p_woh, g_woh);
    cudaGetSymbolAddress((void**)&p_w1h, g_w1h);
    cudaGetSymbolAddress((void**)&p_w2h, g_w2h);

    cudaFuncSetAttribute(k_mma_gemm<0,2,128>, cudaFuncAttributeMaxDynamicSharedMemorySize, GEMM_SMEM_T2);
    cudaFuncSetAttribute(k_mma_gemm<1,1,128>, cudaFuncAttributeMaxDynamicSharedMemorySize, GEMM_SMEM_T1);
    cudaFuncSetAttribute(k_mma_gemm<2,1,128>, cudaFuncAttributeMaxDynamicSharedMemorySize, GEMM_SMEM_T1);
    cudaFuncSetAttribute(k_attn, cudaFuncAttributeMaxDynamicSharedMemorySize, ATTN_SMEM);

    // 1. pos dwconv + residual -> xh (NHWC)
    k_posconv<<<dim3(BB*HH, 2), 256>>>(x, pos_w, pos_b, p_xh);
    // 2. LN1 -> split bf16 y (hi+lo: QKV is 2-term)
    k_ln<<<TOK/8, 256>>>(p_xh, ln1_g, ln1_b, p_yh, p_yl);
    // 3. fused weight transpose (hi only)
    k_wsplit_all<<<640, 256>>>(qkv_w, wo_w, mlp_w1, mlp_w2,
                               p_wqh, p_woh, p_w1h, p_w2h);
    // 4. QKV gemm -> qkv fp32 (2-term, 128-wide N tile)   [profiled launch]
    k_mma_gemm<0,2,128><<<dim3(TOK/128, QKVC/128), 256, GEMM_SMEM_T2>>>(
        p_yh, p_yl, p_wqh, qkv_b, nullptr, p_qkv, nullptr, QKVC, CC);
    // 5. fused window mean(y) + exact routing projections
    k_winroute<<<BB*P2, 256>>>(p_yh, p_yl, qkv_w, qkv_b, p_qwin, p_kwin);
    // 6. routing top-4 (exact logits)
    k_route<<<BB*P2, 64>>>(p_qwin, p_kwin, p_idx);
    // 7. HMMA attention -> att fp32 (NHWC); Q/K/V all bf16-hi
    k_attn<<<BB*P2, 256, ATTN_SMEM>>>(p_qkv, p_idx, p_att);
    // 8. lepe: att + dwconv5x5(v) -> bf16 hi
    k_lepe<<<dim3(BB*HH, 4), 256>>>(p_qkv, lepe_w, lepe_b, p_att, p_ath);
    // 9. wo gemm with residual (1-term): xh = xh + (att+lepe) @ wo + b
    k_mma_gemm<2,1,128><<<dim3(TOK/128, CC/128), 256, GEMM_SMEM_T1>>>(
        p_ath, nullptr, p_woh, wo_b, p_xh, p_xh, nullptr, CC, CC);
    // 10. LN2 -> bf16 y (hi only)
    k_ln<<<TOK/8, 256>>>(p_xh, ln2_g, ln2_b, p_yh, nullptr);
    // 11. mlp1 + gelu (1-term) -> bf16 h1
    k_mma_gemm<1,1,128><<<dim3(TOK/128, 3*CC/128), 256, GEMM_SMEM_T1>>>(
        p_yh, nullptr, p_w1h, mlp_b1, nullptr, nullptr, p_h1h, 3*CC, CC);
    // 12. mlp2 with residual (1-term): xh = xh + h1 @ w2 + b
    k_mma_gemm<2,1,128><<<dim3(TOK/128, CC/128), 256, GEMM_SMEM_T1>>>(
        p_h1h, nullptr, p_w2h, mlp_b2, p_xh, p_xh, nullptr, CC, 3*CC);
    // 13. NHWC -> NCHW
    k_tr<<<dim3((HH*WWI)/32, CC/32, BB), dim3(32, 8)>>>(p_xh, out);
}

// round 15
// speedup vs baseline: 1.3751x; 1.0828x over previous
#include <cuda_runtime.h>
#include <cuda_bf16.h>
#include <cstdint>

#define BB 16
#define CC 128
#define HH 56
#define WWI 56
#define TOK (BB*HH*WWI)          // 50176
#define QKC 128
#define QKVC 384
#define NWIN 7
#define WHS 8
#define P2 49
#define W2 64
#define TOPK 4
#define HEADS 4
#define HD 32
#define SCALE 0.08838834764831845f

typedef unsigned long long ull;

// ---------------- scratch (device globals; no allocation) ----------------
__device__ float g_xh [TOK*CC];
__device__ float g_att[TOK*CC];
__device__ float g_qwin[BB*P2*CC];
__device__ float g_kwin[BB*P2*CC];
__device__ int   g_idx [BB*P2*TOPK];
__device__ __nv_bfloat16 g_qkvb[TOK*QKVC];       // bf16 qkv (q pre-scaled)
// split-bf16 activations
__device__ __nv_bfloat16 g_yh [TOK*CC],  g_yl [TOK*CC];
__device__ __nv_bfloat16 g_ath[TOK*CC];
__device__ __nv_bfloat16 g_h1h[TOK*3*CC];
// bf16 weights, transposed to [N,K] (hi only)
__device__ __nv_bfloat16 g_wqh[QKVC*CC];
__device__ __nv_bfloat16 g_woh[CC*CC];
__device__ __nv_bfloat16 g_w1h[3*CC*CC];
__device__ __nv_bfloat16 g_w2h[CC*3*CC];

// ---------------- helpers ----------------
__device__ __forceinline__ uint32_t smem_u32(const void* p){
    uint32_t a;
    asm("{ .reg .u64 t; cvta.to.shared.u64 t, %1; cvt.u32.u64 %0, t; }" : "=r"(a) : "l"(p));
    return a;
}
__device__ __forceinline__ void ldm_x4(uint32_t& r0,uint32_t& r1,uint32_t& r2,uint32_t& r3, uint32_t addr){
    asm volatile("ldmatrix.sync.aligned.m8n8.x4.shared.b16 {%0,%1,%2,%3}, [%4];"
        : "=r"(r0),"=r"(r1),"=r"(r2),"=r"(r3) : "r"(addr));
}
__device__ __forceinline__ void ldm_x4_t(uint32_t& r0,uint32_t& r1,uint32_t& r2,uint32_t& r3, uint32_t addr){
    asm volatile("ldmatrix.sync.aligned.m8n8.x4.trans.shared.b16 {%0,%1,%2,%3}, [%4];"
        : "=r"(r0),"=r"(r1),"=r"(r2),"=r"(r3) : "r"(addr));
}
__device__ __forceinline__ void mma_bf16(float* d, const uint32_t* a, const uint32_t* b){
    asm volatile("mma.sync.aligned.m16n8k16.row.col.f32.bf16.bf16.f32 "
        "{%0,%1,%2,%3}, {%4,%5,%6,%7}, {%8,%9}, {%0,%1,%2,%3};"
        : "+f"(d[0]),"+f"(d[1]),"+f"(d[2]),"+f"(d[3])
        : "r"(a[0]),"r"(a[1]),"r"(a[2]),"r"(a[3]), "r"(b[0]),"r"(b[1]));
}
__device__ __forceinline__ uint32_t packbf2(float lo, float hi){
    uint32_t r;
    asm("cvt.rn.bf16x2.f32 %0, %1, %2;" : "=r"(r) : "f"(hi), "f"(lo));
    return r;
}
__device__ __forceinline__ float gelu_exact(float v){
    return 0.5f * v * (1.0f + erff(v * 0.70710678118654752f));
}
__device__ __forceinline__ void split_bf16(float v, __nv_bfloat16& h, __nv_bfloat16& l){
    h = __float2bfloat16(v);
    l = __float2bfloat16(v - __bfloat162float(h));
}

// ---------------- fused weight transpose (hi only, one launch) ----------------
__global__ __launch_bounds__(256) void k_wsplit_all(
    const float* __restrict__ qkv_w, const float* __restrict__ wo_w,
    const float* __restrict__ mlp_w1, const float* __restrict__ mlp_w2,
    __nv_bfloat16* __restrict__ wqh,
    __nv_bfloat16* __restrict__ woh,
    __nv_bfloat16* __restrict__ w1h,
    __nv_bfloat16* __restrict__ w2h)
{
    int blk = blockIdx.x;
    const float* src; __nv_bfloat16 *dh; int K, N, base;
    if (blk < 192)      { src = qkv_w;  dh = wqh; K = CC;   N = QKVC; base = 0;   }
    else if (blk < 256) { src = wo_w;   dh = woh; K = CC;   N = CC;   base = 192; }
    else if (blk < 448) { src = mlp_w1; dh = w1h; K = CC;   N = 3*CC; base = 256; }
    else                { src = mlp_w2; dh = w2h; K = 3*CC; N = CC;   base = 448; }
    int i = (blk - base) * 256 + threadIdx.x;
    if (i >= N * K) return;
    int n = i / K, k = i - n * K;
    dh[i] = __float2bfloat16(src[(size_t)k * N + n]);
}

// ---------------- kernel 1: x + dwconv3x3(x) -> xh (NHWC) ----------------
__global__ __launch_bounds__(256) void k_posconv(const float* __restrict__ x,
                                                 const float* __restrict__ pw,
                                                 const float* __restrict__ pb,
                                                 float* __restrict__ xh){
    __shared__ __align__(16) float s[3*64*57];
    int bh = blockIdx.x; int b = bh / HH, h = bh % HH;
    int c0 = blockIdx.y * 64;
    int tid = threadIdx.x;
    for (int l = tid; l < 3*64*56; l += 256){
        int row = l / (64*56);
        int rem = l - row*(64*56);
        int c   = rem / 56;
        int wv  = rem - c*56;
        int hr  = h + row - 1;
        float v = 0.f;
        if (hr >= 0 && hr < HH)
            v = x[((size_t)((b*CC + c0 + c)*HH + hr))*WWI + wv];
        s[row*64*57 + c*57 + wv] = v;
    }
    __syncthreads();
    int c = tid & 63;
    float wgt[9];
    #pragma unroll
    for (int t = 0; t < 9; t++) wgt[t] = pw[(c0 + c)*9 + t];
    float bias = pb[c0 + c];
    for (int l = tid; l < 56*64; l += 256){
        int w = l >> 6;
        float acc = bias;
        #pragma unroll
        for (int ky = 0; ky < 3; ky++){
            const float* srow = &s[ky*64*57 + c*57];
            #pragma unroll
            for (int kx = 0; kx < 3; kx++){
                int ww = w + kx - 1;
                if (ww >= 0 && ww < WWI) acc += wgt[ky*3+kx] * srow[ww];
            }
        }
        acc += s[1*64*57 + c*57 + w];   // residual (center x)
        xh[((size_t)((b*HH + h)*WWI + w))*CC + c0 + c] = acc;
    }
}

// ---------------- kernel 2: LayerNorm over C -> bf16 (lo optional) ----------------
__global__ __launch_bounds__(256) void k_ln(const float* __restrict__ in,
                                            const float* __restrict__ g,
                                            const float* __restrict__ bt,
                                            __nv_bfloat16* __restrict__ oh,
                                            __nv_bfloat16* __restrict__ ol){
    int warp = threadIdx.x >> 5, lane = threadIdx.x & 31;
    int tok = blockIdx.x * 8 + warp;
    const float4* ip = (const float4*)(in + (size_t)tok * CC);
    float4 v = ip[lane];
    float s = v.x + v.y + v.z + v.w;
    float q = v.x*v.x + v.y*v.y + v.z*v.z + v.w*v.w;
    #pragma unroll
    for (int o = 16; o; o >>= 1){
        s += __shfl_xor_sync(0xffffffffu, s, o);
        q += __shfl_xor_sync(0xffffffffu, q, o);
    }
    float m   = s * (1.f/128.f);
    float var = q * (1.f/128.f) - m*m;
    float r   = rsqrtf(var + 1e-6f);
    float4 gg = ((const float4*)g)[lane];
    float4 bb = ((const float4*)bt)[lane];
    float o0 = (v.x - m)*r*gg.x + bb.x;
    float o1 = (v.y - m)*r*gg.y + bb.y;
    float o2 = (v.z - m)*r*gg.z + bb.z;
    float o3 = (v.w - m)*r*gg.w + bb.w;
    __nv_bfloat16 h0,h1,h2,h3,l0,l1,l2,l3;
    split_bf16(o0,h0,l0); split_bf16(o1,h1,l1); split_bf16(o2,h2,l2); split_bf16(o3,h3,l3);
    size_t off = (size_t)tok * CC + lane*4;
    *(__nv_bfloat162*)(oh + off)     = __nv_bfloat162(h0, h1);
    *(__nv_bfloat162*)(oh + off + 2) = __nv_bfloat162(h2, h3);
    if (ol){
        *(__nv_bfloat162*)(ol + off)     = __nv_bfloat162(l0, l1);
        *(__nv_bfloat162*)(ol + off + 2) = __nv_bfloat162(l2, l3);
    }
}

// ---------------- HMMA GEMM: C[M,N] = A[M,K] @ W (128 x 128 tile, 1-term) ----------------
// EPI: 0 = bias -> fp32 C ; 1 = bias+GELU -> bf16 C1 ; 2 = bias+residual R -> fp32 C ;
//      3 = bias, SCALE on first QKC cols -> bf16 C1 (qkv output)
#define ASTR 72   // smem row stride in bf16 (144B: conflict-free ldmatrix)
template<int EPI>
__global__ __launch_bounds__(256) void k_mma_gemm(
    const __nv_bfloat16* __restrict__ Ah,
    const __nv_bfloat16* __restrict__ Bh,
    const float* __restrict__ bias, const float* __restrict__ R,
    float* __restrict__ C, __nv_bfloat16* __restrict__ C1,
    int N, int K)
{
    extern __shared__ __align__(16) __nv_bfloat16 sm[];
    __nv_bfloat16* sAh = sm;
    __nv_bfloat16* sBh = sm + 128*ASTR;

    int tid = threadIdx.x;
    int warp = tid >> 5, lane = tid & 31;
    int wy = warp >> 2, wx = warp & 3;      // 2 warps M x 4 warps N
    int bm = blockIdx.x * 128, bn = blockIdx.y * 128;

    float d[4][4][4];
    #pragma unroll
    for (int mt = 0; mt < 4; mt++)
        #pragma unroll
        for (int nt = 0; nt < 4; nt++)
            #pragma unroll
            for (int i = 0; i < 4; i++) d[mt][nt][i] = 0.f;

    int lr = tid >> 3;          // 0..31
    int lc = (tid & 7) * 8;     // 0..56

    for (int kc = 0; kc < K; kc += 64){
        if (kc) __syncthreads();
        #pragma unroll
        for (int p = 0; p < 4; p++){
            int row = p*32 + lr;
            *(uint4*)&sAh[row*ASTR + lc] = *(const uint4*)(Ah + (size_t)(bm+row)*K + kc + lc);
        }
        #pragma unroll
        for (int p = 0; p < 4; p++){
            int row = p*32 + lr;
            *(uint4*)&sBh[row*ASTR + lc] = *(const uint4*)(Bh + (size_t)(bn+row)*K + kc + lc);
        }
        __syncthreads();
        #pragma unroll
        for (int ks = 0; ks < 4; ks++){
            uint32_t ah[4][4], bh[4][2];
            #pragma unroll
            for (int mt = 0; mt < 4; mt++){
                int r = wy*64 + mt*16 + (lane & 15);
                int c = ks*16 + (lane >> 4)*8;
                ldm_x4(ah[mt][0],ah[mt][1],ah[mt][2],ah[mt][3], smem_u32(&sAh[r*ASTR + c]));
            }
            #pragma unroll
            for (int nn = 0; nn < 2; nn++){
                int g8 = lane >> 3;
                int n = wx*32 + nn*16 + ((g8 >> 1) ? 8 : 0) + (lane & 7);
                int c = ks*16 + (g8 & 1)*8;
                uint32_t r0,r1,r2,r3;
                ldm_x4(r0,r1,r2,r3, smem_u32(&sBh[n*ASTR + c]));
                bh[nn*2+0][0]=r0; bh[nn*2+0][1]=r1; bh[nn*2+1][0]=r2; bh[nn*2+1][1]=r3;
            }
            #pragma unroll
            for (int mt = 0; mt < 4; mt++)
                #pragma unroll
                for (int nt = 0; nt < 4; nt++)
                    mma_bf16(d[mt][nt], ah[mt], bh[nt]);
        }
    }

    int g = lane >> 2, t = lane & 3;
    #pragma unroll
    for (int mt = 0; mt < 4; mt++){
        #pragma unroll
        for (int nt = 0; nt < 4; nt++){
            int c = bn + wx*32 + nt*8 + t*2;
            float b0 = bias[c], b1 = bias[c+1];
            #pragma unroll
            for (int hr = 0; hr < 2; hr++){
                int r = bm + wy*64 + mt*16 + g + hr*8;
                float v0 = d[mt][nt][hr*2+0] + b0;
                float v1 = d[mt][nt][hr*2+1] + b1;
                size_t go = (size_t)r * N + c;
                if (EPI == 0){
                    float2 o; o.x = v0; o.y = v1;
                    *(float2*)(C + go) = o;
                } else if (EPI == 1){
                    v0 = gelu_exact(v0); v1 = gelu_exact(v1);
                    *(__nv_bfloat162*)(C1 + go) =
                        __nv_bfloat162(__float2bfloat16(v0), __float2bfloat16(v1));
                } else if (EPI == 2){
                    float2 rr = *(const float2*)(R + go);
                    float2 o; o.x = v0 + rr.x; o.y = v1 + rr.y;
                    *(float2*)(C + go) = o;
                } else {
                    if (c < QKC){ v0 *= SCALE; v1 *= SCALE; }
                    *(__nv_bfloat162*)(C1 + go) =
                        __nv_bfloat162(__float2bfloat16(v0), __float2bfloat16(v1));
                }
            }
        }
    }
}
#define GEMM_SMEM (2*128*ASTR*2)

// ---------------- kernel 4: fused window mean(y) + exact routing projections ----------------
__global__ __launch_bounds__(256) void k_winroute(const __nv_bfloat16* __restrict__ yh,
                                                  const __nv_bfloat16* __restrict__ yl,
                                                  const float* __restrict__ qkv_w,
                                                  const float* __restrict__ qkv_b,
                                                  float* __restrict__ qwin,
                                                  float* __restrict__ kwin){
    __shared__ float part[256];
    __shared__ float m[CC];
    int bp = blockIdx.x; int b = bp / P2, p = bp - b*P2;
    int tid = threadIdx.x;
    int c = tid & 127, half = tid >> 7;
    int hb = (p / NWIN) * WHS, wb = (p % NWIN) * WHS;
    float s = 0.f;
    #pragma unroll 8
    for (int r = half*32; r < half*32 + 32; r++){
        size_t tok = (size_t)(b*HH + hb + (r >> 3))*WWI + wb + (r & 7);
        s += __bfloat162float(yh[tok*CC + c]) + __bfloat162float(yl[tok*CC + c]);
    }
    part[tid] = s;
    __syncthreads();
    if (tid < CC) m[tid] = (part[tid] + part[tid + 128]) * (1.f/64.f);
    __syncthreads();
    float acc = qkv_b[tid];
    #pragma unroll 8
    for (int k = 0; k < CC; k++)
        acc += m[k] * qkv_w[(size_t)k*QKVC + tid];
    if (tid < QKC) qwin[(size_t)bp*CC + tid] = acc;
    else           kwin[(size_t)bp*CC + (tid - QKC)] = acc;
}

// ---------------- kernel 5: routing logits + top-4 ----------------
__global__ __launch_bounds__(64) void k_route(const float* __restrict__ qwin,
                                              const float* __restrict__ kwin,
                                              int* __restrict__ idx){
    __shared__ float qr[128];
    __shared__ float lg[49];
    int bp = blockIdx.x; int b = bp / P2;
    int t = threadIdx.x;
    qr[t]      = qwin[(size_t)bp*CC + t];
    qr[t + 64] = qwin[(size_t)bp*CC + 64 + t];
    __syncthreads();
    if (t < P2){
        const float* kr = kwin + (size_t)(b*P2 + t)*CC;
        float s = 0.f;
        #pragma unroll 8
        for (int c = 0; c < CC; c++) s += qr[c] * kr[c];
        lg[t] = s;
    }
    __syncthreads();
    if (t == 0){
        unsigned long long used = 0ull;
        for (int r = 0; r < TOPK; r++){
            float best = -1e30f; int bi = 0;
            for (int j = 0; j < P2; j++)
                if (!((used >> j) & 1ull) && lg[j] > best){ best = lg[j]; bi = j; }
            used |= 1ull << bi;
            idx[bp*TOPK + r] = bi;
        }
    }
}

// ---------------- kernel 6: HMMA flash attention (bf16 qkv input) ----------------
#define QSTR 136                 // bf16 row stride (272B), conflict-free ldmatrix
#define QSZ  (64*QSTR)
__global__ __launch_bounds__(256) void k_attn(const __nv_bfloat16* __restrict__ qkvb,
                                              const int* __restrict__ idx,
                                              float* __restrict__ op){
    extern __shared__ __align__(16) __nv_bfloat16 sm[];
    __nv_bfloat16* sQh = sm;
    __nv_bfloat16* sKh = sm + QSZ;
    __nv_bfloat16* sVh = sm + 2*QSZ;

    int bp = blockIdx.x; int b = bp / P2, p = bp - b*P2;
    int tid = threadIdx.x;
    int warp = tid >> 5, lane = tid & 31;
    int h = warp >> 1, qh = warp & 1;
    int g = lane >> 2, t4 = lane & 3;
    int ro = lane & 7, grp = lane >> 3;
    int hb = (p / NWIN)*WHS, wb = (p % NWIN)*WHS;

    // stage Q (already scaled, bf16): 64 x 128, pure uint4 copies
    #pragma unroll
    for (int i = 0; i < 4; i++){
        int li = i*256 + tid;
        int r = li >> 4, c8 = (li & 15)*8;
        size_t tok = (size_t)(b*HH + hb + (r >> 3))*WWI + wb + (r & 7);
        *(uint4*)&sQh[r*QSTR + c8] = *(const uint4*)(qkvb + tok*QKVC + c8);
    }
    __syncthreads();

    uint32_t qah[2][2][4];
    #pragma unroll
    for (int mt = 0; mt < 2; mt++)
        #pragma unroll
        for (int ks = 0; ks < 2; ks++){
            int row = qh*32 + mt*16 + (grp & 1)*8 + ro;
            int col = h*32 + ks*16 + (grp >> 1)*8;
            ldm_x4(qah[mt][ks][0],qah[mt][ks][1],qah[mt][ks][2],qah[mt][ks][3],
                   smem_u32(&sQh[row*QSTR + col]));
        }

    float o[2][4][4];
    #pragma unroll
    for (int mt = 0; mt < 2; mt++)
        #pragma unroll
        for (int nt = 0; nt < 4; nt++)
            #pragma unroll
            for (int i = 0; i < 4; i++) o[mt][nt][i] = 0.f;
    float mst[2][2] = {{-1e30f,-1e30f},{-1e30f,-1e30f}};
    float lst[2][2] = {{0.f,0.f},{0.f,0.f}};

    for (int tt = 0; tt < TOPK; tt++){
        int wsel = idx[bp*TOPK + tt];
        int bh2 = (wsel / NWIN)*WHS, bw2 = (wsel % NWIN)*WHS;
        __syncthreads();
        // stage K,V (bf16): 64 x 256, pure uint4 copies
        #pragma unroll
        for (int i = 0; i < 8; i++){
            int li = i*256 + tid;
            int k = li >> 5, c8 = (li & 31)*8;
            size_t tok = (size_t)(b*HH + bh2 + (k >> 3))*WWI + bw2 + (k & 7);
            uint4 v = *(const uint4*)(qkvb + tok*QKVC + QKC + c8);
            if (c8 < 128) *(uint4*)&sKh[k*QSTR + c8] = v;
            else          *(uint4*)&sVh[k*QSTR + (c8-128)] = v;
        }
        __syncthreads();

        float s[2][8][4];
        #pragma unroll
        for (int mt = 0; mt < 2; mt++)
            #pragma unroll
            for (int nt = 0; nt < 8; nt++)
                #pragma unroll
                for (int i = 0; i < 4; i++) s[mt][nt][i] = 0.f;
        #pragma unroll
        for (int ks = 0; ks < 2; ks++){
            uint32_t kb[8][2];
            int col = h*32 + ks*16 + (grp & 1)*8;
            #pragma unroll
            for (int j = 0; j < 4; j++){
                int row = j*16 + (grp >> 1)*8 + ro;
                uint32_t r0,r1,r2,r3;
                ldm_x4(r0,r1,r2,r3, smem_u32(&sKh[row*QSTR + col]));
                kb[2*j][0]=r0; kb[2*j][1]=r1; kb[2*j+1][0]=r2; kb[2*j+1][1]=r3;
            }
            #pragma unroll
            for (int mt = 0; mt < 2; mt++)
                #pragma unroll
                for (int nt = 0; nt < 8; nt++)
                    mma_bf16(s[mt][nt], qah[mt][ks], kb[nt]);
        }

        uint32_t pa[2][4][4];
        #pragma unroll
        for (int mt = 0; mt < 2; mt++){
            float r0 = -1e30f, r1 = -1e30f;
            #pragma unroll
            for (int nt = 0; nt < 8; nt++){
                r0 = fmaxf(r0, fmaxf(s[mt][nt][0], s[mt][nt][1]));
                r1 = fmaxf(r1, fmaxf(s[mt][nt][2], s[mt][nt][3]));
            }
            r0 = fmaxf(r0, __shfl_xor_sync(0xffffffffu, r0, 1));
            r0 = fmaxf(r0, __shfl_xor_sync(0xffffffffu, r0, 2));
            r1 = fmaxf(r1, __shfl_xor_sync(0xffffffffu, r1, 1));
            r1 = fmaxf(r1, __shfl_xor_sync(0xffffffffu, r1, 2));
            float mn0 = fmaxf(mst[mt][0], r0), mn1 = fmaxf(mst[mt][1], r1);
            float c0 = __expf(mst[mt][0] - mn0), c1 = __expf(mst[mt][1] - mn1);
            mst[mt][0] = mn0; mst[mt][1] = mn1;
            float ls0 = 0.f, ls1 = 0.f;
            #pragma unroll
            for (int nt = 0; nt < 8; nt++){
                float e0 = __expf(s[mt][nt][0] - mn0);
                float e1 = __expf(s[mt][nt][1] - mn0);
                float e2 = __expf(s[mt][nt][2] - mn1);
                float e3 = __expf(s[mt][nt][3] - mn1);
                ls0 += e0 + e1; ls1 += e2 + e3;
                s[mt][nt][0] = e0; s[mt][nt][1] = e1;
                s[mt][nt][2] = e2; s[mt][nt][3] = e3;
            }
            ls0 += __shfl_xor_sync(0xffffffffu, ls0, 1);
            ls0 += __shfl_xor_sync(0xffffffffu, ls0, 2);
            ls1 += __shfl_xor_sync(0xffffffffu, ls1, 1);
            ls1 += __shfl_xor_sync(0xffffffffu, ls1, 2);
            lst[mt][0] = lst[mt][0]*c0 + ls0;
            lst[mt][1] = lst[mt][1]*c1 + ls1;
            #pragma unroll
            for (int nt = 0; nt < 4; nt++){
                o[mt][nt][0] *= c0; o[mt][nt][1] *= c0;
                o[mt][nt][2] *= c1; o[mt][nt][3] *= c1;
            }
            #pragma unroll
            for (int k2 = 0; k2 < 4; k2++){
                pa[mt][k2][0] = packbf2(s[mt][2*k2][0],   s[mt][2*k2][1]);
                pa[mt][k2][1] = packbf2(s[mt][2*k2][2],   s[mt][2*k2][3]);
                pa[mt][k2][2] = packbf2(s[mt][2*k2+1][0], s[mt][2*k2+1][1]);
                pa[mt][k2][3] = packbf2(s[mt][2*k2+1][2], s[mt][2*k2+1][3]);
            }
        }

        #pragma unroll
        for (int k2 = 0; k2 < 4; k2++){
            uint32_t vbh[4][2];
            int row = k2*16 + (grp & 1)*8 + ro;
            #pragma unroll
            for (int np = 0; np < 2; np++){
                int col = h*32 + np*16 + (grp >> 1)*8;
                uint32_t r0,r1,r2,r3;
                ldm_x4_t(r0,r1,r2,r3, smem_u32(&sVh[row*QSTR + col]));
                vbh[2*np][0]=r0; vbh[2*np][1]=r1; vbh[2*np+1][0]=r2; vbh[2*np+1][1]=r3;
            }
            #pragma unroll
            for (int mt = 0; mt < 2; mt++)
                #pragma unroll
                for (int nt = 0; nt < 4; nt++)
                    mma_bf16(o[mt][nt], pa[mt][k2], vbh[nt]);
        }
    }

    #pragma unroll
    for (int mt = 0; mt < 2; mt++){
        float inv0 = 1.f / lst[mt][0], inv1 = 1.f / lst[mt][1];
        int r0 = qh*32 + mt*16 + g, r1 = r0 + 8;
        size_t tok0 = (size_t)(b*HH + hb + (r0 >> 3))*WWI + wb + (r0 & 7);
        size_t tok1 = (size_t)(b*HH + hb + (r1 >> 3))*WWI + wb + (r1 & 7);
        #pragma unroll
        for (int nt = 0; nt < 4; nt++){
            int col = h*32 + nt*8 + t4*2;
            float2 v0; v0.x = o[mt][nt][0]*inv0; v0.y = o[mt][nt][1]*inv0;
            float2 v1; v1.x = o[mt][nt][2]*inv1; v1.y = o[mt][nt][3]*inv1;
            *(float2*)(op + tok0*CC + col) = v0;
            *(float2*)(op + tok1*CC + col) = v1;
        }
    }
}
#define ATTN_SMEM (3*QSZ*2)

// ---------------- kernel 7: LEPE 5x5 dwconv on bf16 v, add att, write bf16 ----------------
__global__ __launch_bounds__(256) void k_lepe(const __nv_bfloat16* __restrict__ qkvb,
                                              const float* __restrict__ lw,
                                              const float* __restrict__ lb,
                                              const float* __restrict__ att,
                                              __nv_bfloat16* __restrict__ oh){
    __shared__ __align__(16) float s[5*32*57];
    int bh = blockIdx.x; int b = bh / HH, h = bh % HH;
    int c0 = blockIdx.y * 32;
    int tid = threadIdx.x;
    for (int l = tid; l < 5*32*56; l += 256){
        int row = l / (32*56);
        int rem = l - row*(32*56);
        int wv  = rem >> 5;
        int c   = rem & 31;
        int hr  = h + row - 2;
        float v = 0.f;
        if (hr >= 0 && hr < HH)
            v = __bfloat162float(qkvb[((size_t)((b*HH + hr)*WWI + wv))*QKVC + 2*QKC + c0 + c]);
        s[row*32*57 + c*57 + wv] = v;
    }
    __syncthreads();
    int c = tid & 31;
    float wg[25];
    #pragma unroll
    for (int t = 0; t < 25; t++) wg[t] = lw[(c0 + c)*25 + t];
    float bias = lb[c0 + c];
    for (int l = tid; l < 56*32; l += 256){
        int w = l >> 5;
        float acc = bias;
        #pragma unroll
        for (int ky = 0; ky < 5; ky++){
            const float* srow = &s[ky*32*57 + c*57];
            #pragma unroll
            for (int kx = 0; kx < 5; kx++){
                int ww = w + kx - 2;
                if (ww >= 0 && ww < WWI) acc += wg[ky*5+kx] * srow[ww];
            }
        }
        size_t go = ((size_t)((b*HH + h)*WWI + w))*CC + c0 + c;
        oh[go] = __float2bfloat16(att[go] + acc);
    }
}

// ---------------- kernel 8: NHWC -> NCHW ----------------
__global__ void k_tr(const float* __restrict__ in, float* __restrict__ out){
    __shared__ float t[32][33];
    int b = blockIdx.z, c0 = blockIdx.y*32, p0 = blockIdx.x*32;
    int tx = threadIdx.x, ty = threadIdx.y;
    #pragma unroll
    for (int u = 0; u < 4; u++)
        t[ty + u*8][tx] = in[((size_t)(b*(HH*WWI) + p0 + ty + u*8))*CC + c0 + tx];
    __syncthreads();
    #pragma unroll
    for (int u = 0; u < 4; u++)
        out[((size_t)(b*CC + c0 + ty + u*8))*(HH*WWI) + p0 + tx] = t[tx][ty + u*8];
}

// ---------------- launcher ----------------
extern "C" void kernel_launch(void* const* d_in, const int* in_sizes, int n_in,
                              void* d_out, int out_size){
    const float* x      = (const float*)d_in[0];
    const float* pos_w  = (const float*)d_in[1];
    const float* pos_b  = (const float*)d_in[2];
    const float* ln1_g  = (const float*)d_in[3];
    const float* ln1_b  = (const float*)d_in[4];
    const float* qkv_w  = (const float*)d_in[5];
    const float* qkv_b  = (const float*)d_in[6];
    const float* lepe_w = (const float*)d_in[7];
    const float* lepe_b = (const float*)d_in[8];
    const float* wo_w   = (const float*)d_in[9];
    const float* wo_b   = (const float*)d_in[10];
    const float* ln2_g  = (const float*)d_in[11];
    const float* ln2_b  = (const float*)d_in[12];
    const float* mlp_w1 = (const float*)d_in[13];
    const float* mlp_b1 = (const float*)d_in[14];
    const float* mlp_w2 = (const float*)d_in[15];
    const float* mlp_b2 = (const float*)d_in[16];
    float* out = (float*)d_out;

    float *p_xh, *p_att, *p_qwin, *p_kwin;
    int *p_idx;
    __nv_bfloat16 *p_qkvb, *p_yh, *p_yl, *p_ath, *p_h1h;
    __nv_bfloat16 *p_wqh, *p_woh, *p_w1h, *p_w2h;
    cudaGetSymbolAddress((void**)&p_xh,   g_xh);
    cudaGetSymbolAddress((void**)&p_att,  g_att);
    cudaGetSymbolAddress((void**)&p_qwin, g_qwin);
    cudaGetSymbolAddress((void**)&p_kwin, g_kwin);
    cudaGetSymbolAddress((void**)&p_idx,  g_idx);
    cudaGetSymbolAddress((void**)&p_qkvb, g_qkvb);
    cudaGetSymbolAddress((void**)&p_yh,   g_yh);
    cudaGetSymbolAddress((void**)&p_yl,   g_yl);
    cudaGetSymbolAddress((void**)&p_ath,  g_ath);
    cudaGetSymbolAddress((void**)&p_h1h,  g_h1h);
    cudaGetSymbolAddress((void**)&p_wqh,  g_wqh);
    cudaGetSymbolAddress((void**)&p_woh,  g_woh);
    cudaGetSymbolAddress((void**)&p_w1h,  g_w1h);
    cudaGetSymbolAddress((void**)&p_w2h,  g_w2h);

    cudaFuncSetAttribute(k_mma_gemm<0>, cudaFuncAttributeMaxDynamicSharedMemorySize, GEMM_SMEM);
    cudaFuncSetAttribute(k_mma_gemm<1>, cudaFuncAttributeMaxDynamicSharedMemorySize, GEMM_SMEM);
    cudaFuncSetAttribute(k_mma_gemm<2>, cudaFuncAttributeMaxDynamicSharedMemorySize, GEMM_SMEM);
    cudaFuncSetAttribute(k_mma_gemm<3>, cudaFuncAttributeMaxDynamicSharedMemorySize, GEMM_SMEM);
    cudaFuncSetAttribute(k_attn, cudaFuncAttributeMaxDynamicSharedMemorySize, ATTN_SMEM);

    // 1. pos dwconv + residual -> xh (NHWC)
    k_posconv<<<dim3(BB*HH, 2), 256>>>(x, pos_w, pos_b, p_xh);
    // 2. LN1 -> split bf16 y (hi+lo: lo used by exact routing)
    k_ln<<<TOK/8, 256>>>(p_xh, ln1_g, ln1_b, p_yh, p_yl);
    // 3. fused weight transpose (hi only)
    k_wsplit_all<<<640, 256>>>(qkv_w, wo_w, mlp_w1, mlp_w2,
                               p_wqh, p_woh, p_w1h, p_w2h);
    // 4. QKV gemm -> bf16 qkv, q pre-scaled (1-term)   [profiled launch]
    k_mma_gemm<3><<<dim3(TOK/128, QKVC/128), 256, GEMM_SMEM>>>(
        p_yh, p_wqh, qkv_b, nullptr, nullptr, p_qkvb, QKVC, CC);
    // 5. fused window mean(y) + exact routing projections
    k_winroute<<<BB*P2, 256>>>(p_yh, p_yl, qkv_w, qkv_b, p_qwin, p_kwin);
    // 6. routing top-4 (exact logits)
    k_route<<<BB*P2, 64>>>(p_qwin, p_kwin, p_idx);
    // 7. HMMA attention on bf16 qkv -> att fp32 (NHWC)
    k_attn<<<BB*P2, 256, ATTN_SMEM>>>(p_qkvb, p_idx, p_att);
    // 8. lepe: att + dwconv5x5(v_bf16) -> bf16
    k_lepe<<<dim3(BB*HH, 4), 256>>>(p_qkvb, lepe_w, lepe_b, p_att, p_ath);
    // 9. wo gemm with residual: xh = xh + (att+lepe) @ wo + b
    k_mma_gemm<2><<<dim3(TOK/128, CC/128), 256, GEMM_SMEM>>>(
        p_ath, p_woh, wo_b, p_xh, p_xh, nullptr, CC, CC);
    // 10. LN2 -> bf16 y (hi only)
    k_ln<<<TOK/8, 256>>>(p_xh, ln2_g, ln2_b, p_yh, nullptr);
    // 11. mlp1 + gelu -> bf16 h1
    k_mma_gemm<1><<<dim3(TOK/128, 3*CC/128), 256, GEMM_SMEM>>>(
        p_yh, p_w1h, mlp_b1, nullptr, nullptr, p_h1h, 3*CC, CC);
    // 12. mlp2 with residual: xh = xh + h1 @ w2 + b
    k_mma_gemm<2><<<dim3(TOK/128, CC/128), 256, GEMM_SMEM>>>(
        p_h1h, p_w2h, mlp_b2, p_xh, p_xh, nullptr, CC, 3*CC);
    // 13. NHWC -> NCHW
    k_tr<<<dim3((HH*WWI)/32, CC/32, BB), dim3(32, 8)>>>(p_xh, out);
}